// round 12
// baseline (speedup 1.0000x reference)
#include <cuda_runtime.h>
#include <math.h>

#define B 8
#define N 4096
#define DF 768
#define K1 8
#define K2 2
#define DS 128
#define BK (B*K1)        // 64
#define NS (BK*K2)       // 128 slot rows
#define SCALE 0.088388347648318447f
#define EPS_SA 1e-8f
#define OBJ_SIZE (NS*DS)

// ------------------- scratch (device globals) -------------------
__device__ float g_mean[B*N];
__device__ float g_var[B*N];
__device__ float g_s[BK*N];
__device__ float g_sm[BK];                       // sum_j s_j * m_j per bk
__device__ __align__(16) float g_T[BK*DF];       // sum_j s_j * x_j per bk
__device__ float g_slots[NS*DS];
__device__ __align__(16) float g_aD[BK*DF];      // delta a-vector per bk
__device__ float g_sAD[BK];
__device__ float g_beD[BK];
__device__ __align__(16) float g_acc0[BK*DF];    // slot-0 accumulator
__device__ float g_z0[BK];
__device__ float g_d0[BK];
__device__ float g_cv[DS];
__device__ float g_kg[DS];                       // Wk @ ln_in_g
__device__ float g_kb[DS];                       // Wk @ ln_in_b
// transposed weights
__device__ float g_WvT[DF*DS];
__device__ float g_WihT[DS*3*DS];
__device__ float g_WhhT[DS*3*DS];
__device__ float g_W1T[DS*4*DS];
__device__ float g_W2T[4*DS*DS];

// paired warp reduction: on exit all lanes hold x=sum(x), y=sum(y).
__device__ __forceinline__ void warp_reduce2(float& x, float& y, int lane) {
    float xo = __shfl_xor_sync(0xffffffffu, x, 16);
    float yo = __shfl_xor_sync(0xffffffffu, y, 16);
    float v  = (lane < 16) ? (x + xo) : (y + yo);
    #pragma unroll
    for (int off = 8; off; off >>= 1) v += __shfl_xor_sync(0xffffffffu, v, off);
    x = __shfl_sync(0xffffffffu, v, 0);
    y = __shfl_sync(0xffffffffu, v, 16);
}

__device__ __forceinline__ float block_reduce_256(float v, float* red, int tid) {
    red[tid] = v; __syncthreads();
    #pragma unroll
    for (int h = 128; h > 0; h >>= 1) {
        if (tid < h) red[tid] += red[tid + h];
        __syncthreads();
    }
    float r = red[0];
    __syncthreads();
    return r;
}

// ------------------- one-time kernels -------------------
// per-token mean/var over DF.  grid B*N/8 blocks of 256 (warp/row)
__global__ void stats_kernel(const float* __restrict__ tokens) {
    int row  = blockIdx.x * 8 + (threadIdx.x >> 5);
    int lane = threadIdx.x & 31;
    const float4* xp = (const float4*)(tokens + (size_t)row * DF);
    float s = 0.f, s2 = 0.f;
    #pragma unroll
    for (int k = 0; k < 6; k++) {
        float4 v = xp[k*32 + lane];
        s  += v.x + v.y + v.z + v.w;
        s2 += v.x*v.x + v.y*v.y + v.z*v.z + v.w*v.w;
    }
    #pragma unroll
    for (int off = 16; off; off >>= 1) {
        s  += __shfl_xor_sync(0xffffffffu, s,  off);
        s2 += __shfl_xor_sync(0xffffffffu, s2, off);
    }
    if (lane == 0) {
        float m = s * (1.f/DF);
        g_mean[row] = m;
        g_var[row]  = s2 * (1.f/DF) - m*m;
    }
}

// fused denom + s; blocks 0-31 additionally compute kg/kb.  grid BK blocks of 256
__global__ void dss_kernel(const float* __restrict__ masks, const float* __restrict__ Wk,
                           const float* __restrict__ ig, const float* __restrict__ ib) {
    __shared__ float red[256];
    int bk = blockIdx.x, b = bk >> 3, tid = threadIdx.x;
    float s = 0.f;
    for (int j = tid; j < N; j += 256) s += masks[(size_t)bk*N + j];
    float denom = block_reduce_256(s, red, tid) * (1.f/N);
    int good = denom > 1e-6f;
    float inv = 1.f / (denom + 1e-6f);
    for (int j = tid; j < N; j += 256) {
        float w = good ? masks[(size_t)bk*N + j] * inv : 1.0f;
        float v = g_var[b*N + j];
        g_s[(size_t)bk*N + j] = w * rsqrtf(w*w*v + 1e-5f);
    }
    if (bk < 32) {   // warp per output col: kg = Wk@ig (bk<16), kb = Wk@ib
        int w = tid >> 5, lane = tid & 31;
        int c = (bk & 15)*8 + w;
        const float* vv = (bk < 16) ? ig : ib;
        float acc = 0.f;
        #pragma unroll
        for (int k = 0; k < 24; k++) {
            int f = k*32 + lane;
            acc += Wk[(size_t)c*DF + f] * vv[f];
        }
        #pragma unroll
        for (int off = 16; off; off >>= 1) acc += __shfl_xor_sync(0xffffffffu, acc, off);
        if (lane == 0) { if (bk < 16) g_kg[c] = acc; else g_kb[c] = acc; }
    }
}

// transpose weight matrices (Wv, Wih, Whh, W1, W2)
__global__ void tr_kernel(const float* __restrict__ Wv,
                          const float* __restrict__ Wih, const float* __restrict__ Whh,
                          const float* __restrict__ W1, const float* __restrict__ W2) {
    int i = blockIdx.x*256 + threadIdx.x;
    if (i < DF*DS) { int f = i/DS, o = i%DS; g_WvT[i] = Wv[o*DF + f]; return; }
    i -= DF*DS;
    if (i < DS*3*DS) { int f = i/(3*DS), o = i%(3*DS); g_WihT[i] = Wih[o*DS + f]; return; }
    i -= DS*3*DS;
    if (i < DS*3*DS) { int f = i/(3*DS), o = i%(3*DS); g_WhhT[i] = Whh[o*DS + f]; return; }
    i -= DS*3*DS;
    if (i < DS*4*DS) { int f = i/(4*DS), o = i%(4*DS); g_W1T[i] = W1[o*DS + f]; return; }
    i -= DS*4*DS;
    if (i < 4*DS*DS) { int o = i/DS, t = i%DS; g_W2T[i] = W2[t*4*DS + o]; return; }
}

// cv = Wv @ ln_in_b.  grid 16 blocks x 256 (warp per output col)
__global__ void cv_kernel(const float* __restrict__ Wv, const float* __restrict__ lnb) {
    int col  = blockIdx.x*8 + (threadIdx.x >> 5);
    int lane = threadIdx.x & 31;
    float a = 0.f;
    #pragma unroll
    for (int k = 0; k < 24; k++) {
        int f = k*32 + lane;
        a += Wv[(size_t)col*DF + f] * lnb[f];
    }
    #pragma unroll
    for (int off = 16; off; off >>= 1) a += __shfl_xor_sync(0xffffffffu, a, off);
    if (lane == 0) g_cv[col] = a;
}

// ------------------- per-iteration kernels -------------------
// grid = BK*3 blocks: (bk, ff-slice). All blocks redo the tiny LN/q; slices split Wk matvec.
__global__ void qa_kernel(const float* __restrict__ ps, const float* __restrict__ eps,
                          const float* __restrict__ Wq, const float* __restrict__ Wk,
                          const float* __restrict__ sg, const float* __restrict__ sb,
                          const float* __restrict__ ig, const float* __restrict__ ib,
                          int first) {
    __shared__ float sn[2][DS], qsh[2][DS], qD[DS], red[256];
    int bk = blockIdx.x / 3, ff = blockIdx.x % 3;
    int tid = threadIdx.x;
    int half = tid >> 7, t = tid & 127;
    int r = bk*2 + half;
    float val;
    if (first) {
        val = ps[bk*DS + t] + 0.01f * eps[r*DS + t];
        if (ff == 0) g_slots[r*DS + t] = val;
    } else {
        val = g_slots[r*DS + t];
    }
    // segmented mean/var per half
    red[tid] = val; __syncthreads();
    #pragma unroll
    for (int h = 64; h; h >>= 1) { if (t < h) red[tid] += red[tid + h]; __syncthreads(); }
    float m = red[half*128] * (1.f/DS);
    __syncthreads();
    float dv = val - m;
    red[tid] = dv*dv; __syncthreads();
    #pragma unroll
    for (int h = 64; h; h >>= 1) { if (t < h) red[tid] += red[tid + h]; __syncthreads(); }
    float rstd = rsqrtf(red[half*128] * (1.f/DS) + 1e-5f);
    __syncthreads();
    sn[half][t] = dv * rstd * sg[t] + sb[t];
    __syncthreads();
    {   // q = sn @ Wq^T
        float q0 = 0.f, q1 = 0.f;
        #pragma unroll 4
        for (int f = 0; f < DS; f += 2) {
            q0 += Wq[t*DS + f]   * sn[half][f];
            q1 += Wq[t*DS + f+1] * sn[half][f+1];
        }
        qsh[half][t] = q0 + q1;
    }
    __syncthreads();
    if (tid < DS) qD[tid] = qsh[0][tid] - qsh[1][tid];
    __syncthreads();
    // slice matvec: f = ff*256 + tid
    {
        int f = ff*256 + tid;
        float r0=0.f, r1=0.f, r2=0.f, r3=0.f;
        #pragma unroll 4
        for (int c = 0; c < DS; c += 4) {
            r0 += Wk[c*DF + f]     * qD[c];
            r1 += Wk[(c+1)*DF + f] * qD[c+1];
            r2 += Wk[(c+2)*DF + f] * qD[c+2];
            r3 += Wk[(c+3)*DF + f] * qD[c+3];
        }
        float raw = (r0+r1)+(r2+r3);
        g_aD[(size_t)bk*DF + f]   = raw * ig[f];
        g_acc0[(size_t)bk*DF + f] = 0.f;
        if (first) g_T[(size_t)bk*DF + f] = 0.f;
    }
    if (ff == 0) {   // sums via precomputed kg/kb (exact reassociation of sum over f)
        float psm = (tid < DS) ? qD[tid]*g_kg[tid] : 0.f;
        float pbe = (tid < DS) ? qD[tid]*g_kb[tid] : 0.f;
        float ts = block_reduce_256(psm, red, tid);
        float tb = block_reduce_256(pbe, red, tid);
        if (tid == 0) {
            g_sAD[bk] = ts; g_beD[bk] = tb;
            g_z0[bk] = 0.f; g_d0[bk] = 0.f;
            if (first) g_sm[bk] = 0.f;
        }
    }
}

// Warp-autonomous big kernel: grid 32 pairs x 32 tiles = 1024 blocks of 128.
// Warp owns 32 tokens end-to-end; no barriers in the main loop.
// MODE: 0 = first iter (accumulate T, sm), 1 = middle, 2 = last (write gating).
template<int MODE>
__global__ void __launch_bounds__(128) big_kernel(const float* __restrict__ tokens,
                                                  const float* __restrict__ masks,
                                                  float* __restrict__ out) {
    __shared__ float sacc[2*DF];
    int p = blockIdx.x & 31, tile = blockIdx.x >> 5;
    int bk0 = 2*p, bk1 = bk0 + 1, b = p >> 2;
    int tid = threadIdx.x, w = tid >> 5, lane = tid & 31;

    const float4* a0p = (const float4*)(g_aD + (size_t)bk0*DF);
    const float4* a1p = (const float4*)(g_aD + (size_t)bk1*DF);
    float4 a0v[6], a1v[6], acc0[6], acc1[6];
    float4 accT0[6], accT1[6];
    #pragma unroll
    for (int k = 0; k < 6; k++) {
        a0v[k] = a0p[k*32 + lane];
        a1v[k] = a1p[k*32 + lane];
        acc0[k] = make_float4(0.f,0.f,0.f,0.f);
        acc1[k] = make_float4(0.f,0.f,0.f,0.f);
        if (MODE == 0) {
            accT0[k] = make_float4(0.f,0.f,0.f,0.f);
            accT1[k] = make_float4(0.f,0.f,0.f,0.f);
        }
    }
    float sA0 = g_sAD[bk0], sA1 = g_sAD[bk1];
    float be0 = g_beD[bk0], be1 = g_beD[bk1];
    float z0=0.f, z1=0.f, dd0=0.f, dd1=0.f, sm0=0.f, sm1=0.f;
    float keep0 = 0.f, keep1 = 0.f;
    int j0 = tile*128 + w*32;

    for (int t = 0; t < 32; t++) {
        int j = j0 + t;
        const float4* gx = (const float4*)(tokens + (size_t)(b*N + j)*DF);
        float4 xv[6];
        float d0 = 0.f, d1 = 0.f;
        #pragma unroll
        for (int k = 0; k < 6; k++) {
            xv[k] = gx[k*32 + lane];
            d0 += a0v[k].x*xv[k].x + a0v[k].y*xv[k].y + a0v[k].z*xv[k].z + a0v[k].w*xv[k].w;
            d1 += a1v[k].x*xv[k].x + a1v[k].y*xv[k].y + a1v[k].z*xv[k].z + a1v[k].w*xv[k].w;
        }
        warp_reduce2(d0, d1, lane);
        float s0 = g_s[(size_t)bk0*N + j], s1 = g_s[(size_t)bk1*N + j];
        float m  = g_mean[b*N + j];
        float p0 = 1.f/(1.f + __expf(-(SCALE*(s0*(d0 - m*sA0) + be0))));
        float p1 = 1.f/(1.f + __expf(-(SCALE*(s1*(d1 - m*sA1) + be1))));
        float at0 = p0 + EPS_SA, at1 = p1 + EPS_SA;
        float c0 = at0*s0, c1 = at1*s1;
        z0 += at0; z1 += at1; dd0 += c0*m; dd1 += c1*m;
        if (MODE == 0) { sm0 += s0*m; sm1 += s1*m; }
        if (MODE == 2) { if (t == lane) { keep0 = p0; keep1 = p1; } }
        #pragma unroll
        for (int k = 0; k < 6; k++) {
            acc0[k].x += c0*xv[k].x; acc0[k].y += c0*xv[k].y;
            acc0[k].z += c0*xv[k].z; acc0[k].w += c0*xv[k].w;
            acc1[k].x += c1*xv[k].x; acc1[k].y += c1*xv[k].y;
            acc1[k].z += c1*xv[k].z; acc1[k].w += c1*xv[k].w;
            if (MODE == 0) {
                accT0[k].x += s0*xv[k].x; accT0[k].y += s0*xv[k].y;
                accT0[k].z += s0*xv[k].z; accT0[k].w += s0*xv[k].w;
                accT1[k].x += s1*xv[k].x; accT1[k].y += s1*xv[k].y;
                accT1[k].z += s1*xv[k].z; accT1[k].w += s1*xv[k].w;
            }
        }
    }

    if (MODE == 2) {   // child_gating writes, coalesced per warp
        int j = j0 + lane;
        float mk0 = masks[(size_t)bk0*N + j];
        float mk1 = masks[(size_t)bk1*N + j];
        out[OBJ_SIZE + (size_t)(bk0*2)*N + j]   = (keep0 + EPS_SA)*mk0;
        out[OBJ_SIZE + (size_t)(bk0*2+1)*N + j] = (1.f - keep0 + EPS_SA)*mk0;
        out[OBJ_SIZE + (size_t)(bk1*2)*N + j]   = (keep1 + EPS_SA)*mk1;
        out[OBJ_SIZE + (size_t)(bk1*2+1)*N + j] = (1.f - keep1 + EPS_SA)*mk1;
    }

    // epilogue: block-combine in smem, then global atomics
    for (int i = tid; i < 2*DF; i += 128) sacc[i] = 0.f;
    __syncthreads();
    #pragma unroll
    for (int k = 0; k < 6; k++) {
        int f = (k*32 + lane)*4;
        atomicAdd(&sacc[f],      acc0[k].x); atomicAdd(&sacc[f+1],    acc0[k].y);
        atomicAdd(&sacc[f+2],    acc0[k].z); atomicAdd(&sacc[f+3],    acc0[k].w);
        atomicAdd(&sacc[DF+f],   acc1[k].x); atomicAdd(&sacc[DF+f+1], acc1[k].y);
        atomicAdd(&sacc[DF+f+2], acc1[k].z); atomicAdd(&sacc[DF+f+3], acc1[k].w);
    }
    __syncthreads();
    for (int i = tid; i < DF; i += 128) {
        atomicAdd(&g_acc0[(size_t)bk0*DF + i], sacc[i]);
        atomicAdd(&g_acc0[(size_t)bk1*DF + i], sacc[DF + i]);
    }
    if (lane == 0) {   // z/dd identical across lanes; each warp adds once
        atomicAdd(&g_z0[bk0], z0);  atomicAdd(&g_z0[bk1], z1);
        atomicAdd(&g_d0[bk0], dd0); atomicAdd(&g_d0[bk1], dd1);
        if (MODE == 0) { atomicAdd(&g_sm[bk0], sm0); atomicAdd(&g_sm[bk1], sm1); }
    }
    if (MODE == 0) {   // second round for T, reusing sacc
        __syncthreads();
        for (int i = tid; i < 2*DF; i += 128) sacc[i] = 0.f;
        __syncthreads();
        #pragma unroll
        for (int k = 0; k < 6; k++) {
            int f = (k*32 + lane)*4;
            atomicAdd(&sacc[f],      accT0[k].x); atomicAdd(&sacc[f+1],    accT0[k].y);
            atomicAdd(&sacc[f+2],    accT0[k].z); atomicAdd(&sacc[f+3],    accT0[k].w);
            atomicAdd(&sacc[DF+f],   accT1[k].x); atomicAdd(&sacc[DF+f+1], accT1[k].y);
            atomicAdd(&sacc[DF+f+2], accT1[k].z); atomicAdd(&sacc[DF+f+3], accT1[k].w);
        }
        __syncthreads();
        for (int i = tid; i < DF; i += 128) {
            atomicAdd(&g_T[(size_t)bk0*DF + i], sacc[i]);
            atomicAdd(&g_T[(size_t)bk1*DF + i], sacc[DF + i]);
        }
    }
}

// upd: 256 threads per slot row; f-split halves (unchanged from R10)
__global__ void __launch_bounds__(256) upd_kernel(const float* __restrict__ ig,
                           const float* __restrict__ bih, const float* __restrict__ bhh,
                           const float* __restrict__ mg,  const float* __restrict__ mb,
                           const float* __restrict__ b1,  const float* __restrict__ b2,
                           float* __restrict__ out, int last) {
    __shared__ float gv[DF];
    __shared__ float su[DS], sh[DS], shh[DS], snews[DS];
    __shared__ float sy[4*DS];
    __shared__ float part[6][2][DS];
    __shared__ float red[DS];
    int r = blockIdx.x, tid = threadIdx.x;
    int col = tid & 127, half = tid >> 7;
    int bk = r >> 1, i = r & 1;
    const float ONE = 1.f + 2.f*EPS_SA;
    float Z0 = g_z0[bk], D0 = g_d0[bk];
    float Z = i ? (4096.f*ONE - Z0) : Z0;
    float D = i ? (g_sm[bk]*ONE - D0) : D0;
    for (int f = tid; f < DF; f += 256) {
        float A = g_acc0[(size_t)bk*DF + f];
        if (i) A = g_T[(size_t)bk*DF + f]*ONE - A;
        gv[f] = ig[f] * (A - D);
    }
    if (tid < DS) sh[tid] = g_slots[r*DS + tid];
    __syncthreads();
    {
        float a0=0.f,a1=0.f,a2=0.f,a3=0.f;
        int f0 = half*384;
        #pragma unroll 8
        for (int f = f0; f < f0+384; f += 4) {
            a0 += g_WvT[(f+0)*DS + col] * gv[f+0];
            a1 += g_WvT[(f+1)*DS + col] * gv[f+1];
            a2 += g_WvT[(f+2)*DS + col] * gv[f+2];
            a3 += g_WvT[(f+3)*DS + col] * gv[f+3];
        }
        part[0][half][col] = (a0+a1)+(a2+a3);
    }
    __syncthreads();
    if (tid < DS) su[tid] = (part[0][0][tid] + part[0][1][tid]) / Z + g_cv[tid];
    __syncthreads();
    {
        float gi0=0.f, gi1=0.f, gi2=0.f, gh0=0.f, gh1=0.f, gh2=0.f;
        int f0 = half*64;
        #pragma unroll 4
        for (int f = f0; f < f0+64; f++) {
            float uf = su[f], hf = sh[f];
            gi0 += g_WihT[f*(3*DS) + col]*uf;
            gi1 += g_WihT[f*(3*DS) + DS + col]*uf;
            gi2 += g_WihT[f*(3*DS) + 2*DS + col]*uf;
            gh0 += g_WhhT[f*(3*DS) + col]*hf;
            gh1 += g_WhhT[f*(3*DS) + DS + col]*hf;
            gh2 += g_WhhT[f*(3*DS) + 2*DS + col]*hf;
        }
        part[0][half][col] = gi0; part[1][half][col] = gi1; part[2][half][col] = gi2;
        part[3][half][col] = gh0; part[4][half][col] = gh1; part[5][half][col] = gh2;
    }
    __syncthreads();
    if (tid < DS) {
        int t = tid;
        float gi0 = bih[t]        + part[0][0][t] + part[0][1][t];
        float gi1 = bih[DS+t]     + part[1][0][t] + part[1][1][t];
        float gi2 = bih[2*DS+t]   + part[2][0][t] + part[2][1][t];
        float gh0 = bhh[t]        + part[3][0][t] + part[3][1][t];
        float gh1 = bhh[DS+t]     + part[4][0][t] + part[4][1][t];
        float gh2 = bhh[2*DS+t]   + part[5][0][t] + part[5][1][t];
        float rr = 1.f / (1.f + __expf(-(gi0 + gh0)));
        float zz = 1.f / (1.f + __expf(-(gi1 + gh1)));
        float nn = tanhf(gi2 + rr*gh2);
        snews[t] = (1.f - zz)*nn + zz*sh[t];
    }
    __syncthreads();
    if (tid < DS) red[tid] = snews[tid];
    __syncthreads();
    #pragma unroll
    for (int h2 = 64; h2; h2 >>= 1) { if (tid < h2) red[tid] += red[tid+h2]; __syncthreads(); }
    float m = red[0] * (1.f/DS);
    __syncthreads();
    if (tid < DS) { float dv = snews[tid] - m; red[tid] = dv*dv; }
    __syncthreads();
    #pragma unroll
    for (int h2 = 64; h2; h2 >>= 1) { if (tid < h2) red[tid] += red[tid+h2]; __syncthreads(); }
    float rstd = rsqrtf(red[0]*(1.f/DS) + 1e-5f);
    __syncthreads();
    if (tid < DS) shh[tid] = (snews[tid] - m)*rstd*mg[tid] + mb[tid];
    __syncthreads();
    {
        float aa = b1[tid], ab = b1[tid+256];
        #pragma unroll 4
        for (int f = 0; f < DS; f++) {
            float s = shh[f];
            aa += g_W1T[f*(4*DS) + tid]       * s;
            ab += g_W1T[f*(4*DS) + tid + 256] * s;
        }
        sy[tid]       = 0.5f * aa * (1.f + erff(aa * 0.70710678118654752f));
        sy[tid + 256] = 0.5f * ab * (1.f + erff(ab * 0.70710678118654752f));
    }
    __syncthreads();
    {
        float a0=0.f,a1=0.f,a2=0.f,a3=0.f;
        int o0 = half*256;
        #pragma unroll 8
        for (int o = o0; o < o0+256; o += 4) {
            a0 += g_W2T[(o+0)*DS + col]*sy[o+0];
            a1 += g_W2T[(o+1)*DS + col]*sy[o+1];
            a2 += g_W2T[(o+2)*DS + col]*sy[o+2];
            a3 += g_W2T[(o+3)*DS + col]*sy[o+3];
        }
        part[0][half][col] = (a0+a1)+(a2+a3);
    }
    __syncthreads();
    if (tid < DS) {
        float o2 = b2[tid] + part[0][0][tid] + part[0][1][tid];
        g_slots[r*DS + tid] = o2;
        if (last) out[r*DS + tid] = o2;
    }
}

// ------------------- launch -------------------
extern "C" void kernel_launch(void* const* d_in, const int* in_sizes, int n_in,
                              void* d_out, int out_size) {
    const float* tokens = (const float*)d_in[0];
    const float* pslots = (const float*)d_in[1];
    const float* masks  = (const float*)d_in[2];
    const float* eps    = (const float*)d_in[3];
    const float* ig     = (const float*)d_in[4];
    const float* ib     = (const float*)d_in[5];
    const float* sg     = (const float*)d_in[6];
    const float* sb     = (const float*)d_in[7];
    const float* Wq     = (const float*)d_in[8];
    const float* Wk     = (const float*)d_in[9];
    const float* Wv     = (const float*)d_in[10];
    const float* Wih    = (const float*)d_in[11];
    const float* Whh    = (const float*)d_in[12];
    const float* bih    = (const float*)d_in[13];
    const float* bhh    = (const float*)d_in[14];
    const float* mg     = (const float*)d_in[15];
    const float* mb     = (const float*)d_in[16];
    const float* W1     = (const float*)d_in[17];
    const float* b1     = (const float*)d_in[18];
    const float* W2     = (const float*)d_in[19];
    const float* b2     = (const float*)d_in[20];
    float* out = (float*)d_out;

    stats_kernel<<<B*N/8, 256>>>(tokens);                               // 0
    dss_kernel<<<BK, 256>>>(masks, Wk, ig, ib);                         // 1
    qa_kernel<<<BK*3, 256>>>(pslots, eps, Wq, Wk, sg, sb, ig, ib, 1);   // 2
    big_kernel<0><<<32*32, 128>>>(tokens, masks, out);                  // 3 (profiled)
    tr_kernel<<<(DF*DS + 2*DS*3*DS + 2*DS*4*DS + 255)/256, 256>>>(Wv, Wih, Whh, W1, W2); // 4
    cv_kernel<<<16, 256>>>(Wv, ib);                                     // 5
    upd_kernel<<<NS, 256>>>(ig, bih, bhh, mg, mb, b1, b2, out, 0);      // 6

    // iteration 1
    qa_kernel<<<BK*3, 256>>>(pslots, eps, Wq, Wk, sg, sb, ig, ib, 0);
    big_kernel<1><<<32*32, 128>>>(tokens, masks, out);
    upd_kernel<<<NS, 256>>>(ig, bih, bhh, mg, mb, b1, b2, out, 0);
    // iteration 2 (last)
    qa_kernel<<<BK*3, 256>>>(pslots, eps, Wq, Wk, sg, sb, ig, ib, 0);
    big_kernel<2><<<32*32, 128>>>(tokens, masks, out);
    upd_kernel<<<NS, 256>>>(ig, bih, bhh, mg, mb, b1, b2, out, 1);
}

// round 13
// speedup vs baseline: 1.1792x; 1.1792x over previous
#include <cuda_runtime.h>
#include <math.h>

#define B 8
#define N 4096
#define DF 768
#define K1 8
#define K2 2
#define DS 128
#define BK (B*K1)        // 64
#define NS (BK*K2)       // 128 slot rows
#define SCALE 0.088388347648318447f
#define EPS_SA 1e-8f
#define OBJ_SIZE (NS*DS)

// ------------------- scratch (device globals) -------------------
__device__ float g_mean[B*N];
__device__ float g_var[B*N];
__device__ float g_s[BK*N];
__device__ float g_sm[BK];                       // sum_j s_j * m_j per bk
__device__ __align__(16) float g_T[BK*DF];       // sum_j s_j * x_j per bk
__device__ float g_slots[NS*DS];
__device__ __align__(16) float g_aD[BK*DF];      // delta a-vector per bk
__device__ float g_sAD[BK];
__device__ float g_beD[BK];
__device__ __align__(16) float g_acc0[BK*DF];    // slot-0 accumulator
__device__ float g_z0[BK];
__device__ float g_d0[BK];
__device__ float g_cv[DS];
__device__ float g_kg[DS];                       // Wk @ ln_in_g
__device__ float g_kb[DS];                       // Wk @ ln_in_b
// transposed weights
__device__ float g_WvT[DF*DS];
__device__ float g_WihT[DS*3*DS];
__device__ float g_WhhT[DS*3*DS];
__device__ float g_W1T[DS*4*DS];
__device__ float g_W2T[4*DS*DS];

// paired warp reduction: on exit all lanes hold x=sum(x), y=sum(y).
__device__ __forceinline__ void warp_reduce2(float& x, float& y, int lane) {
    float xo = __shfl_xor_sync(0xffffffffu, x, 16);
    float yo = __shfl_xor_sync(0xffffffffu, y, 16);
    float v  = (lane < 16) ? (x + xo) : (y + yo);
    #pragma unroll
    for (int off = 8; off; off >>= 1) v += __shfl_xor_sync(0xffffffffu, v, off);
    x = __shfl_sync(0xffffffffu, v, 0);
    y = __shfl_sync(0xffffffffu, v, 16);
}

__device__ __forceinline__ float block_reduce_256(float v, float* red, int tid) {
    red[tid] = v; __syncthreads();
    #pragma unroll
    for (int h = 128; h > 0; h >>= 1) {
        if (tid < h) red[tid] += red[tid + h];
        __syncthreads();
    }
    float r = red[0];
    __syncthreads();
    return r;
}

// ------------------- one-time kernels -------------------
// per-token mean/var over DF.  grid B*N/8 blocks of 256 (warp/row)
__global__ void stats_kernel(const float* __restrict__ tokens) {
    int row  = blockIdx.x * 8 + (threadIdx.x >> 5);
    int lane = threadIdx.x & 31;
    const float4* xp = (const float4*)(tokens + (size_t)row * DF);
    float s = 0.f, s2 = 0.f;
    #pragma unroll
    for (int k = 0; k < 6; k++) {
        float4 v = xp[k*32 + lane];
        s  += v.x + v.y + v.z + v.w;
        s2 += v.x*v.x + v.y*v.y + v.z*v.z + v.w*v.w;
    }
    #pragma unroll
    for (int off = 16; off; off >>= 1) {
        s  += __shfl_xor_sync(0xffffffffu, s,  off);
        s2 += __shfl_xor_sync(0xffffffffu, s2, off);
    }
    if (lane == 0) {
        float m = s * (1.f/DF);
        g_mean[row] = m;
        g_var[row]  = s2 * (1.f/DF) - m*m;
    }
}

// fused denom + s; blocks 0-31 additionally compute kg/kb.  grid BK blocks of 256
__global__ void dss_kernel(const float* __restrict__ masks, const float* __restrict__ Wk,
                           const float* __restrict__ ig, const float* __restrict__ ib) {
    __shared__ float red[256];
    int bk = blockIdx.x, b = bk >> 3, tid = threadIdx.x;
    float s = 0.f;
    for (int j = tid; j < N; j += 256) s += masks[(size_t)bk*N + j];
    float denom = block_reduce_256(s, red, tid) * (1.f/N);
    int good = denom > 1e-6f;
    float inv = 1.f / (denom + 1e-6f);
    for (int j = tid; j < N; j += 256) {
        float w = good ? masks[(size_t)bk*N + j] * inv : 1.0f;
        float v = g_var[b*N + j];
        g_s[(size_t)bk*N + j] = w * rsqrtf(w*w*v + 1e-5f);
    }
    if (bk < 32) {   // warp per output col: kg = Wk@ig (bk<16), kb = Wk@ib
        int w = tid >> 5, lane = tid & 31;
        int c = (bk & 15)*8 + w;
        const float* vv = (bk < 16) ? ig : ib;
        float acc = 0.f;
        #pragma unroll
        for (int k = 0; k < 24; k++) {
            int f = k*32 + lane;
            acc += Wk[(size_t)c*DF + f] * vv[f];
        }
        #pragma unroll
        for (int off = 16; off; off >>= 1) acc += __shfl_xor_sync(0xffffffffu, acc, off);
        if (lane == 0) { if (bk < 16) g_kg[c] = acc; else g_kb[c] = acc; }
    }
}

// transpose weight matrices (Wv, Wih, Whh, W1, W2)
__global__ void tr_kernel(const float* __restrict__ Wv,
                          const float* __restrict__ Wih, const float* __restrict__ Whh,
                          const float* __restrict__ W1, const float* __restrict__ W2) {
    int i = blockIdx.x*256 + threadIdx.x;
    if (i < DF*DS) { int f = i/DS, o = i%DS; g_WvT[i] = Wv[o*DF + f]; return; }
    i -= DF*DS;
    if (i < DS*3*DS) { int f = i/(3*DS), o = i%(3*DS); g_WihT[i] = Wih[o*DS + f]; return; }
    i -= DS*3*DS;
    if (i < DS*3*DS) { int f = i/(3*DS), o = i%(3*DS); g_WhhT[i] = Whh[o*DS + f]; return; }
    i -= DS*3*DS;
    if (i < DS*4*DS) { int f = i/(4*DS), o = i%(4*DS); g_W1T[i] = W1[o*DS + f]; return; }
    i -= DS*4*DS;
    if (i < 4*DS*DS) { int o = i/DS, t = i%DS; g_W2T[i] = W2[t*4*DS + o]; return; }
}

// cv = Wv @ ln_in_b.  grid 16 blocks x 256 (warp per output col)
__global__ void cv_kernel(const float* __restrict__ Wv, const float* __restrict__ lnb) {
    int col  = blockIdx.x*8 + (threadIdx.x >> 5);
    int lane = threadIdx.x & 31;
    float a = 0.f;
    #pragma unroll
    for (int k = 0; k < 24; k++) {
        int f = k*32 + lane;
        a += Wv[(size_t)col*DF + f] * lnb[f];
    }
    #pragma unroll
    for (int off = 16; off; off >>= 1) a += __shfl_xor_sync(0xffffffffu, a, off);
    if (lane == 0) g_cv[col] = a;
}

// ------------------- per-iteration kernels -------------------
// grid = BK*3 blocks: (bk, ff-slice). All blocks redo the tiny LN/q; slices split Wk matvec.
__global__ void qa_kernel(const float* __restrict__ ps, const float* __restrict__ eps,
                          const float* __restrict__ Wq, const float* __restrict__ Wk,
                          const float* __restrict__ sg, const float* __restrict__ sb,
                          const float* __restrict__ ig, const float* __restrict__ ib,
                          int first) {
    __shared__ float sn[2][DS], qsh[2][DS], qD[DS], red[256];
    int bk = blockIdx.x / 3, ff = blockIdx.x % 3;
    int tid = threadIdx.x;
    int half = tid >> 7, t = tid & 127;
    int r = bk*2 + half;
    float val;
    if (first) {
        val = ps[bk*DS + t] + 0.01f * eps[r*DS + t];
        if (ff == 0) g_slots[r*DS + t] = val;
    } else {
        val = g_slots[r*DS + t];
    }
    // segmented mean/var per half
    red[tid] = val; __syncthreads();
    #pragma unroll
    for (int h = 64; h; h >>= 1) { if (t < h) red[tid] += red[tid + h]; __syncthreads(); }
    float m = red[half*128] * (1.f/DS);
    __syncthreads();
    float dv = val - m;
    red[tid] = dv*dv; __syncthreads();
    #pragma unroll
    for (int h = 64; h; h >>= 1) { if (t < h) red[tid] += red[tid + h]; __syncthreads(); }
    float rstd = rsqrtf(red[half*128] * (1.f/DS) + 1e-5f);
    __syncthreads();
    sn[half][t] = dv * rstd * sg[t] + sb[t];
    __syncthreads();
    {   // q = sn @ Wq^T
        float q0 = 0.f, q1 = 0.f;
        #pragma unroll 4
        for (int f = 0; f < DS; f += 2) {
            q0 += Wq[t*DS + f]   * sn[half][f];
            q1 += Wq[t*DS + f+1] * sn[half][f+1];
        }
        qsh[half][t] = q0 + q1;
    }
    __syncthreads();
    if (tid < DS) qD[tid] = qsh[0][tid] - qsh[1][tid];
    __syncthreads();
    // slice matvec: f = ff*256 + tid
    {
        int f = ff*256 + tid;
        float r0=0.f, r1=0.f, r2=0.f, r3=0.f;
        #pragma unroll 4
        for (int c = 0; c < DS; c += 4) {
            r0 += Wk[c*DF + f]     * qD[c];
            r1 += Wk[(c+1)*DF + f] * qD[c+1];
            r2 += Wk[(c+2)*DF + f] * qD[c+2];
            r3 += Wk[(c+3)*DF + f] * qD[c+3];
        }
        float raw = (r0+r1)+(r2+r3);
        g_aD[(size_t)bk*DF + f]   = raw * ig[f];
        g_acc0[(size_t)bk*DF + f] = 0.f;
        if (first) g_T[(size_t)bk*DF + f] = 0.f;
    }
    if (ff == 0) {   // sums via precomputed kg/kb (exact reassociation of sum over f)
        float psm = (tid < DS) ? qD[tid]*g_kg[tid] : 0.f;
        float pbe = (tid < DS) ? qD[tid]*g_kb[tid] : 0.f;
        float ts = block_reduce_256(psm, red, tid);
        float tb = block_reduce_256(pbe, red, tid);
        if (tid == 0) {
            g_sAD[bk] = ts; g_beD[bk] = tb;
            g_z0[bk] = 0.f; g_d0[bk] = 0.f;
            if (first) g_sm[bk] = 0.f;
        }
    }
}

// Phased big kernel (R10 verbatim): dots computed during staging.
// block = 256 thr (8 warps), pair of bks, 128 tokens in 4 chunks of 32.
__global__ void __launch_bounds__(256) big_kernel(const float* __restrict__ tokens,
                                                  const float* __restrict__ masks,
                                                  float* __restrict__ out,
                                                  int first, int last) {
    extern __shared__ float4 sm4[];
    float4* xs  = sm4;                   // 32*193 = 6176 float4
    float*  dtp = (float*)(sm4 + 6176);  // 64 floats

    int p = blockIdx.x & 31, tile = blockIdx.x >> 5;
    int bk0 = 2*p, bk1 = bk0 + 1, b = p >> 2;
    int tid = threadIdx.x, w = tid >> 5, lane = tid & 31;

    const float4* a0p = (const float4*)(g_aD + (size_t)bk0*DF);
    const float4* a1p = (const float4*)(g_aD + (size_t)bk1*DF);
    float4 a0v[6], a1v[6];
    #pragma unroll
    for (int k = 0; k < 6; k++) {
        a0v[k] = a0p[k*32 + lane];
        a1v[k] = a1p[k*32 + lane];
    }
    float sA0 = g_sAD[bk0], sA1 = g_sAD[bk1];
    float be0 = g_beD[bk0], be1 = g_beD[bk1];
    float4 acc0 = {0,0,0,0}, acc1 = {0,0,0,0};
    float4 accT0 = {0,0,0,0}, accT1 = {0,0,0,0};
    float z0=0.f, z1=0.f, dd0=0.f, dd1=0.f, sm0=0.f, sm1=0.f;

    for (int cc = 0; cc < 4; cc++) {
        int j0 = tile*128 + cc*32;
        // Phase A: warp w stages tokens w*4..w*4+3 AND computes their delta-dots
        #pragma unroll
        for (int u = 0; u < 4; u++) {
            int t = w*4 + u;
            const float4* gx = (const float4*)(tokens + (size_t)(b*N + j0 + t)*DF);
            float d0 = 0.f, d1 = 0.f;
            #pragma unroll
            for (int k = 0; k < 6; k++) {
                float4 x = gx[k*32 + lane];
                xs[t*193 + k*32 + lane] = x;
                d0 += a0v[k].x*x.x + a0v[k].y*x.y + a0v[k].z*x.z + a0v[k].w*x.w;
                d1 += a1v[k].x*x.x + a1v[k].y*x.y + a1v[k].z*x.z + a1v[k].w*x.w;
            }
            warp_reduce2(d0, d1, lane);
            if (lane == 0) { dtp[t] = d0; dtp[32 + t] = d1; }
        }
        __syncthreads();
        // Phase C: sigmoid weights (all warps redundantly; lane = token)
        int j = j0 + lane;
        float d0 = dtp[lane], d1 = dtp[32 + lane];
        float s0 = g_s[(size_t)bk0*N + j], s1 = g_s[(size_t)bk1*N + j];
        float m  = g_mean[b*N + j];
        float p0 = 1.f/(1.f + __expf(-(SCALE*(s0*(d0 - m*sA0) + be0))));
        float p1 = 1.f/(1.f + __expf(-(SCALE*(s1*(d1 - m*sA1) + be1))));
        float at0 = p0 + EPS_SA, at1 = p1 + EPS_SA;
        float c0 = at0*s0, c1 = at1*s1;
        if (w == 0) {
            z0 += at0; z1 += at1; dd0 += c0*m; dd1 += c1*m;
            if (first) { sm0 += s0*m; sm1 += s1*m; }
            if (last) {
                float mk0 = masks[(size_t)bk0*N + j];
                float mk1 = masks[(size_t)bk1*N + j];
                out[OBJ_SIZE + (size_t)(bk0*2)*N + j]   = at0*mk0;
                out[OBJ_SIZE + (size_t)(bk0*2+1)*N + j] = (1.f - p0 + EPS_SA)*mk0;
                out[OBJ_SIZE + (size_t)(bk1*2)*N + j]   = at1*mk1;
                out[OBJ_SIZE + (size_t)(bk1*2+1)*N + j] = (1.f - p1 + EPS_SA)*mk1;
            }
        }
        // Phase D: f-major accumulate (thread owns one float4 column; shfl weights)
        if (tid < 192) {
            if (first) {
                #pragma unroll
                for (int t = 0; t < 32; t++) {
                    float4 x = xs[t*193 + tid];
                    float c0t = __shfl_sync(0xffffffffu, c0, t);
                    float c1t = __shfl_sync(0xffffffffu, c1, t);
                    float s0t = __shfl_sync(0xffffffffu, s0, t);
                    float s1t = __shfl_sync(0xffffffffu, s1, t);
                    acc0.x += c0t*x.x;  acc0.y += c0t*x.y;  acc0.z += c0t*x.z;  acc0.w += c0t*x.w;
                    acc1.x += c1t*x.x;  acc1.y += c1t*x.y;  acc1.z += c1t*x.z;  acc1.w += c1t*x.w;
                    accT0.x += s0t*x.x; accT0.y += s0t*x.y; accT0.z += s0t*x.z; accT0.w += s0t*x.w;
                    accT1.x += s1t*x.x; accT1.y += s1t*x.y; accT1.z += s1t*x.z; accT1.w += s1t*x.w;
                }
            } else {
                #pragma unroll
                for (int t = 0; t < 32; t++) {
                    float4 x = xs[t*193 + tid];
                    float c0t = __shfl_sync(0xffffffffu, c0, t);
                    float c1t = __shfl_sync(0xffffffffu, c1, t);
                    acc0.x += c0t*x.x; acc0.y += c0t*x.y; acc0.z += c0t*x.z; acc0.w += c0t*x.w;
                    acc1.x += c1t*x.x; acc1.y += c1t*x.y; acc1.z += c1t*x.z; acc1.w += c1t*x.w;
                }
            }
        }
        __syncthreads();   // protect xs & dtp before next chunk
    }

    // epilogue: global accumulation
    if (tid < 192) {
        size_t f0 = (size_t)bk0*DF + tid*4;
        size_t f1 = (size_t)bk1*DF + tid*4;
        atomicAdd(&g_acc0[f0+0], acc0.x); atomicAdd(&g_acc0[f0+1], acc0.y);
        atomicAdd(&g_acc0[f0+2], acc0.z); atomicAdd(&g_acc0[f0+3], acc0.w);
        atomicAdd(&g_acc0[f1+0], acc1.x); atomicAdd(&g_acc0[f1+1], acc1.y);
        atomicAdd(&g_acc0[f1+2], acc1.z); atomicAdd(&g_acc0[f1+3], acc1.w);
        if (first) {
            atomicAdd(&g_T[f0+0], accT0.x); atomicAdd(&g_T[f0+1], accT0.y);
            atomicAdd(&g_T[f0+2], accT0.z); atomicAdd(&g_T[f0+3], accT0.w);
            atomicAdd(&g_T[f1+0], accT1.x); atomicAdd(&g_T[f1+1], accT1.y);
            atomicAdd(&g_T[f1+2], accT1.z); atomicAdd(&g_T[f1+3], accT1.w);
        }
    }
    if (w == 0) {
        warp_reduce2(z0, z1, lane);
        warp_reduce2(dd0, dd1, lane);
        if (first) warp_reduce2(sm0, sm1, lane);
        if (lane == 0) {
            atomicAdd(&g_z0[bk0], z0);  atomicAdd(&g_z0[bk1], z1);
            atomicAdd(&g_d0[bk0], dd0); atomicAdd(&g_d0[bk1], dd1);
            if (first) { atomicAdd(&g_sm[bk0], sm0); atomicAdd(&g_sm[bk1], sm1); }
        }
    }
}

// upd v3: 512 threads per slot row; 4-way f-splits shorten all chains.
__global__ void __launch_bounds__(512) upd_kernel(const float* __restrict__ ig,
                           const float* __restrict__ bih, const float* __restrict__ bhh,
                           const float* __restrict__ mg,  const float* __restrict__ mb,
                           const float* __restrict__ b1,  const float* __restrict__ b2,
                           float* __restrict__ out, int last) {
    __shared__ float gv[DF];
    __shared__ float su[DS], sh[DS], shh[DS], snews[DS];
    __shared__ float sy[4*DS];
    __shared__ float part[6][4][DS];
    __shared__ float red[DS];
    int r = blockIdx.x, tid = threadIdx.x;
    int col = tid & 127, q = tid >> 7;          // quarter 0..3
    int bk = r >> 1, i = r & 1;
    const float ONE = 1.f + 2.f*EPS_SA;
    float Z0 = g_z0[bk], D0 = g_d0[bk];
    float Z = i ? (4096.f*ONE - Z0) : Z0;
    float D = i ? (g_sm[bk]*ONE - D0) : D0;
    for (int f = tid; f < DF; f += 512) {
        float A = g_acc0[(size_t)bk*DF + f];
        if (i) A = g_T[(size_t)bk*DF + f]*ONE - A;
        gv[f] = ig[f] * (A - D);
    }
    if (tid < DS) sh[tid] = g_slots[r*DS + tid];
    __syncthreads();
    // Wv matvec: quarters split the 768 f-range (192 each)
    {
        float a0=0.f,a1=0.f,a2=0.f,a3=0.f;
        int f0 = q*192;
        #pragma unroll 8
        for (int f = f0; f < f0+192; f += 4) {
            a0 += g_WvT[(f+0)*DS + col] * gv[f+0];
            a1 += g_WvT[(f+1)*DS + col] * gv[f+1];
            a2 += g_WvT[(f+2)*DS + col] * gv[f+2];
            a3 += g_WvT[(f+3)*DS + col] * gv[f+3];
        }
        part[0][q][col] = (a0+a1)+(a2+a3);
    }
    __syncthreads();
    if (tid < DS) su[tid] = ((part[0][0][tid] + part[0][1][tid]) +
                             (part[0][2][tid] + part[0][3][tid])) / Z + g_cv[tid];
    __syncthreads();
    // GRU: quarters split the 128 f-range (32 each), 6 accumulators
    {
        float gi0=0.f, gi1=0.f, gi2=0.f, gh0=0.f, gh1=0.f, gh2=0.f;
        int f0 = q*32;
        #pragma unroll 4
        for (int f = f0; f < f0+32; f++) {
            float uf = su[f], hf = sh[f];
            gi0 += g_WihT[f*(3*DS) + col]*uf;
            gi1 += g_WihT[f*(3*DS) + DS + col]*uf;
            gi2 += g_WihT[f*(3*DS) + 2*DS + col]*uf;
            gh0 += g_WhhT[f*(3*DS) + col]*hf;
            gh1 += g_WhhT[f*(3*DS) + DS + col]*hf;
            gh2 += g_WhhT[f*(3*DS) + 2*DS + col]*hf;
        }
        part[0][q][col] = gi0; part[1][q][col] = gi1; part[2][q][col] = gi2;
        part[3][q][col] = gh0; part[4][q][col] = gh1; part[5][q][col] = gh2;
    }
    __syncthreads();
    if (tid < DS) {
        int t = tid;
        float gi0 = bih[t]      + (part[0][0][t]+part[0][1][t])+(part[0][2][t]+part[0][3][t]);
        float gi1 = bih[DS+t]   + (part[1][0][t]+part[1][1][t])+(part[1][2][t]+part[1][3][t]);
        float gi2 = bih[2*DS+t] + (part[2][0][t]+part[2][1][t])+(part[2][2][t]+part[2][3][t]);
        float gh0 = bhh[t]      + (part[3][0][t]+part[3][1][t])+(part[3][2][t]+part[3][3][t]);
        float gh1 = bhh[DS+t]   + (part[4][0][t]+part[4][1][t])+(part[4][2][t]+part[4][3][t]);
        float gh2 = bhh[2*DS+t] + (part[5][0][t]+part[5][1][t])+(part[5][2][t]+part[5][3][t]);
        float rr = 1.f / (1.f + __expf(-(gi0 + gh0)));
        float zz = 1.f / (1.f + __expf(-(gi1 + gh1)));
        float nn = tanhf(gi2 + rr*gh2);
        snews[t] = (1.f - zz)*nn + zz*sh[t];
    }
    __syncthreads();
    // LN over the 128 news values
    if (tid < DS) red[tid] = snews[tid];
    __syncthreads();
    #pragma unroll
    for (int h2 = 64; h2; h2 >>= 1) { if (tid < h2) red[tid] += red[tid+h2]; __syncthreads(); }
    float m = red[0] * (1.f/DS);
    __syncthreads();
    if (tid < DS) { float dv = snews[tid] - m; red[tid] = dv*dv; }
    __syncthreads();
    #pragma unroll
    for (int h2 = 64; h2; h2 >>= 1) { if (tid < h2) red[tid] += red[tid+h2]; __syncthreads(); }
    float rstd = rsqrtf(red[0]*(1.f/DS) + 1e-5f);
    __syncthreads();
    if (tid < DS) shh[tid] = (snews[tid] - m)*rstd*mg[tid] + mb[tid];
    __syncthreads();
    // MLP W1: one output per thread (512 outputs)
    {
        float aa = b1[tid];
        #pragma unroll 4
        for (int f = 0; f < DS; f++) aa += g_W1T[f*(4*DS) + tid] * shh[f];
        sy[tid] = 0.5f * aa * (1.f + erff(aa * 0.70710678118654752f));
    }
    __syncthreads();
    // W2: quarters split the 512 o-range (128 each)
    {
        float a0=0.f,a1=0.f,a2=0.f,a3=0.f;
        int o0 = q*128;
        #pragma unroll 8
        for (int o = o0; o < o0+128; o += 4) {
            a0 += g_W2T[(o+0)*DS + col]*sy[o+0];
            a1 += g_W2T[(o+1)*DS + col]*sy[o+1];
            a2 += g_W2T[(o+2)*DS + col]*sy[o+2];
            a3 += g_W2T[(o+3)*DS + col]*sy[o+3];
        }
        part[0][q][col] = (a0+a1)+(a2+a3);
    }
    __syncthreads();
    if (tid < DS) {
        float o2 = b2[tid] + (part[0][0][tid]+part[0][1][tid])
                           + (part[0][2][tid]+part[0][3][tid]);
        g_slots[r*DS + tid] = o2;
        if (last) out[r*DS + tid] = o2;
    }
}

// ------------------- launch -------------------
#define BIG_SMEM (6176*16 + 256)   // 99072 bytes

extern "C" void kernel_launch(void* const* d_in, const int* in_sizes, int n_in,
                              void* d_out, int out_size) {
    const float* tokens = (const float*)d_in[0];
    const float* pslots = (const float*)d_in[1];
    const float* masks  = (const float*)d_in[2];
    const float* eps    = (const float*)d_in[3];
    const float* ig     = (const float*)d_in[4];
    const float* ib     = (const float*)d_in[5];
    const float* sg     = (const float*)d_in[6];
    const float* sb     = (const float*)d_in[7];
    const float* Wq     = (const float*)d_in[8];
    const float* Wk     = (const float*)d_in[9];
    const float* Wv     = (const float*)d_in[10];
    const float* Wih    = (const float*)d_in[11];
    const float* Whh    = (const float*)d_in[12];
    const float* bih    = (const float*)d_in[13];
    const float* bhh    = (const float*)d_in[14];
    const float* mg     = (const float*)d_in[15];
    const float* mb     = (const float*)d_in[16];
    const float* W1     = (const float*)d_in[17];
    const float* b1     = (const float*)d_in[18];
    const float* W2     = (const float*)d_in[19];
    const float* b2     = (const float*)d_in[20];
    float* out = (float*)d_out;

    cudaFuncSetAttribute(big_kernel, cudaFuncAttributeMaxDynamicSharedMemorySize, BIG_SMEM);

    stats_kernel<<<B*N/8, 256>>>(tokens);                               // 0
    dss_kernel<<<BK, 256>>>(masks, Wk, ig, ib);                         // 1
    qa_kernel<<<BK*3, 256>>>(pslots, eps, Wq, Wk, sg, sb, ig, ib, 1);   // 2
    big_kernel<<<32*32, 256, BIG_SMEM>>>(tokens, masks, out, 1, 0);     // 3 (profiled)
    tr_kernel<<<(DF*DS + 2*DS*3*DS + 2*DS*4*DS + 255)/256, 256>>>(Wv, Wih, Whh, W1, W2); // 4
    cv_kernel<<<16, 256>>>(Wv, ib);                                     // 5
    upd_kernel<<<NS, 512>>>(ig, bih, bhh, mg, mb, b1, b2, out, 0);      // 6

    // iteration 1
    qa_kernel<<<BK*3, 256>>>(pslots, eps, Wq, Wk, sg, sb, ig, ib, 0);
    big_kernel<<<32*32, 256, BIG_SMEM>>>(tokens, masks, out, 0, 0);
    upd_kernel<<<NS, 512>>>(ig, bih, bhh, mg, mb, b1, b2, out, 0);
    // iteration 2 (last)
    qa_kernel<<<BK*3, 256>>>(pslots, eps, Wq, Wk, sg, sb, ig, ib, 0);
    big_kernel<<<32*32, 256, BIG_SMEM>>>(tokens, masks, out, 0, 1);
    upd_kernel<<<NS, 512>>>(ig, bih, bhh, mg, mb, b1, b2, out, 1);
}

// round 14
// speedup vs baseline: 1.5204x; 1.2894x over previous
#include <cuda_runtime.h>
#include <cuda_fp16.h>
#include <math.h>

#define B 8
#define N 4096
#define DF 768
#define K1 8
#define K2 2
#define DS 128
#define BK (B*K1)        // 64
#define NS (BK*K2)       // 128 slot rows
#define SCALE 0.088388347648318447f
#define EPS_SA 1e-8f
#define OBJ_SIZE (NS*DS)

// ------------------- scratch (device globals) -------------------
__device__ float g_mean[B*N];
__device__ float g_var[B*N];
__device__ float g_s[BK*N];
__device__ float g_sm[BK];
__device__ __align__(16) float g_T[BK*DF];
__device__ float g_slots[NS*DS];
__device__ __align__(16) float g_aD[BK*DF];
__device__ float g_sAD[BK];
__device__ float g_beD[BK];
__device__ __align__(16) float g_acc0[BK*DF];
__device__ float g_z0[BK];
__device__ float g_d0[BK];
__device__ float g_cv[DS];
__device__ float g_kg[DS];
__device__ float g_kb[DS];
__device__ __align__(16) __half g_tok16[(size_t)B*N*DF];   // fp16 tokens (50MB)
// transposed weights
__device__ float g_WvT[DF*DS];
__device__ float g_WihT[DS*3*DS];
__device__ float g_WhhT[DS*3*DS];
__device__ float g_W1T[DS*4*DS];
__device__ float g_W2T[4*DS*DS];

__device__ __forceinline__ void warp_reduce2(float& x, float& y, int lane) {
    float xo = __shfl_xor_sync(0xffffffffu, x, 16);
    float yo = __shfl_xor_sync(0xffffffffu, y, 16);
    float v  = (lane < 16) ? (x + xo) : (y + yo);
    #pragma unroll
    for (int off = 8; off; off >>= 1) v += __shfl_xor_sync(0xffffffffu, v, off);
    x = __shfl_sync(0xffffffffu, v, 0);
    y = __shfl_sync(0xffffffffu, v, 16);
}

__device__ __forceinline__ float block_reduce_256(float v, float* red, int tid) {
    red[tid] = v; __syncthreads();
    #pragma unroll
    for (int h = 128; h > 0; h >>= 1) {
        if (tid < h) red[tid] += red[tid + h];
        __syncthreads();
    }
    float r = red[0];
    __syncthreads();
    return r;
}

__device__ __forceinline__ float2 h2f(unsigned u) {
    __half2 h; *(unsigned*)&h = u;
    return __half22float2(h);
}

// ------------------- one-time kernels -------------------
// per-token mean/var over DF + fp16 conversion.  grid B*N/8 blocks of 256 (warp/row)
__global__ void stats_kernel(const float* __restrict__ tokens) {
    int row  = blockIdx.x * 8 + (threadIdx.x >> 5);
    int lane = threadIdx.x & 31;
    const float4* xp = (const float4*)(tokens + (size_t)row * DF);
    uint2* hp = (uint2*)(g_tok16 + (size_t)row * DF);
    float s = 0.f, s2 = 0.f;
    #pragma unroll
    for (int k = 0; k < 6; k++) {
        float4 v = xp[k*32 + lane];
        s  += v.x + v.y + v.z + v.w;
        s2 += v.x*v.x + v.y*v.y + v.z*v.z + v.w*v.w;
        __half2 h0 = __floats2half2_rn(v.x, v.y);
        __half2 h1 = __floats2half2_rn(v.z, v.w);
        uint2 u; u.x = *(unsigned*)&h0; u.y = *(unsigned*)&h1;
        hp[k*32 + lane] = u;
    }
    #pragma unroll
    for (int off = 16; off; off >>= 1) {
        s  += __shfl_xor_sync(0xffffffffu, s,  off);
        s2 += __shfl_xor_sync(0xffffffffu, s2, off);
    }
    if (lane == 0) {
        float m = s * (1.f/DF);
        g_mean[row] = m;
        g_var[row]  = s2 * (1.f/DF) - m*m;
    }
}

// fused denom + s; blocks 0-31 additionally compute kg/kb.  grid BK blocks of 256
__global__ void dss_kernel(const float* __restrict__ masks, const float* __restrict__ Wk,
                           const float* __restrict__ ig, const float* __restrict__ ib) {
    __shared__ float red[256];
    int bk = blockIdx.x, b = bk >> 3, tid = threadIdx.x;
    float s = 0.f;
    for (int j = tid; j < N; j += 256) s += masks[(size_t)bk*N + j];
    float denom = block_reduce_256(s, red, tid) * (1.f/N);
    int good = denom > 1e-6f;
    float inv = 1.f / (denom + 1e-6f);
    for (int j = tid; j < N; j += 256) {
        float w = good ? masks[(size_t)bk*N + j] * inv : 1.0f;
        float v = g_var[b*N + j];
        g_s[(size_t)bk*N + j] = w * rsqrtf(w*w*v + 1e-5f);
    }
    if (bk < 32) {
        int w = tid >> 5, lane = tid & 31;
        int c = (bk & 15)*8 + w;
        const float* vv = (bk < 16) ? ig : ib;
        float acc = 0.f;
        #pragma unroll
        for (int k = 0; k < 24; k++) {
            int f = k*32 + lane;
            acc += Wk[(size_t)c*DF + f] * vv[f];
        }
        #pragma unroll
        for (int off = 16; off; off >>= 1) acc += __shfl_xor_sync(0xffffffffu, acc, off);
        if (lane == 0) { if (bk < 16) g_kg[c] = acc; else g_kb[c] = acc; }
    }
}

// transpose weight matrices (Wv, Wih, Whh, W1, W2)
__global__ void tr_kernel(const float* __restrict__ Wv,
                          const float* __restrict__ Wih, const float* __restrict__ Whh,
                          const float* __restrict__ W1, const float* __restrict__ W2) {
    int i = blockIdx.x*256 + threadIdx.x;
    if (i < DF*DS) { int f = i/DS, o = i%DS; g_WvT[i] = Wv[o*DF + f]; return; }
    i -= DF*DS;
    if (i < DS*3*DS) { int f = i/(3*DS), o = i%(3*DS); g_WihT[i] = Wih[o*DS + f]; return; }
    i -= DS*3*DS;
    if (i < DS*3*DS) { int f = i/(3*DS), o = i%(3*DS); g_WhhT[i] = Whh[o*DS + f]; return; }
    i -= DS*3*DS;
    if (i < DS*4*DS) { int f = i/(4*DS), o = i%(4*DS); g_W1T[i] = W1[o*DS + f]; return; }
    i -= DS*4*DS;
    if (i < 4*DS*DS) { int o = i/DS, t = i%DS; g_W2T[i] = W2[t*4*DS + o]; return; }
}

// cv = Wv @ ln_in_b.  grid 16 blocks x 256 (warp per output col)
__global__ void cv_kernel(const float* __restrict__ Wv, const float* __restrict__ lnb) {
    int col  = blockIdx.x*8 + (threadIdx.x >> 5);
    int lane = threadIdx.x & 31;
    float a = 0.f;
    #pragma unroll
    for (int k = 0; k < 24; k++) {
        int f = k*32 + lane;
        a += Wv[(size_t)col*DF + f] * lnb[f];
    }
    #pragma unroll
    for (int off = 16; off; off >>= 1) a += __shfl_xor_sync(0xffffffffu, a, off);
    if (lane == 0) g_cv[col] = a;
}

// ------------------- per-iteration kernels -------------------
// grid = BK*3 blocks: (bk, ff-slice).
__global__ void qa_kernel(const float* __restrict__ ps, const float* __restrict__ eps,
                          const float* __restrict__ Wq, const float* __restrict__ Wk,
                          const float* __restrict__ sg, const float* __restrict__ sb,
                          const float* __restrict__ ig, const float* __restrict__ ib,
                          int first) {
    __shared__ float sn[2][DS], qsh[2][DS], qD[DS], red[256];
    int bk = blockIdx.x / 3, ff = blockIdx.x % 3;
    int tid = threadIdx.x;
    int half = tid >> 7, t = tid & 127;
    int r = bk*2 + half;
    float val;
    if (first) {
        val = ps[bk*DS + t] + 0.01f * eps[r*DS + t];
        if (ff == 0) g_slots[r*DS + t] = val;
    } else {
        val = g_slots[r*DS + t];
    }
    red[tid] = val; __syncthreads();
    #pragma unroll
    for (int h = 64; h; h >>= 1) { if (t < h) red[tid] += red[tid + h]; __syncthreads(); }
    float m = red[half*128] * (1.f/DS);
    __syncthreads();
    float dv = val - m;
    red[tid] = dv*dv; __syncthreads();
    #pragma unroll
    for (int h = 64; h; h >>= 1) { if (t < h) red[tid] += red[tid + h]; __syncthreads(); }
    float rstd = rsqrtf(red[half*128] * (1.f/DS) + 1e-5f);
    __syncthreads();
    sn[half][t] = dv * rstd * sg[t] + sb[t];
    __syncthreads();
    {
        float q0 = 0.f, q1 = 0.f;
        #pragma unroll 4
        for (int f = 0; f < DS; f += 2) {
            q0 += Wq[t*DS + f]   * sn[half][f];
            q1 += Wq[t*DS + f+1] * sn[half][f+1];
        }
        qsh[half][t] = q0 + q1;
    }
    __syncthreads();
    if (tid < DS) qD[tid] = qsh[0][tid] - qsh[1][tid];
    __syncthreads();
    {
        int f = ff*256 + tid;
        float r0=0.f, r1=0.f, r2=0.f, r3=0.f;
        #pragma unroll 4
        for (int c = 0; c < DS; c += 4) {
            r0 += Wk[c*DF + f]     * qD[c];
            r1 += Wk[(c+1)*DF + f] * qD[c+1];
            r2 += Wk[(c+2)*DF + f] * qD[c+2];
            r3 += Wk[(c+3)*DF + f] * qD[c+3];
        }
        float raw = (r0+r1)+(r2+r3);
        g_aD[(size_t)bk*DF + f]   = raw * ig[f];
        g_acc0[(size_t)bk*DF + f] = 0.f;
        if (first) g_T[(size_t)bk*DF + f] = 0.f;
    }
    if (ff == 0) {
        float psm = (tid < DS) ? qD[tid]*g_kg[tid] : 0.f;
        float pbe = (tid < DS) ? qD[tid]*g_kb[tid] : 0.f;
        float ts = block_reduce_256(psm, red, tid);
        float tb = block_reduce_256(pbe, red, tid);
        if (tid == 0) {
            g_sAD[bk] = ts; g_beD[bk] = tb;
            g_z0[bk] = 0.f; g_d0[bk] = 0.f;
            if (first) g_sm[bk] = 0.f;
        }
    }
}

// Phased big kernel on fp16 tokens.  block = 256, pair of bks, 4 chunks of 32 tokens.
// smem: xs 32 rows x 97 uint4 (96 data + 1 pad) = 49.7KB; dtp 64 floats.
__global__ void __launch_bounds__(256) big_kernel(const float* __restrict__ masks,
                                                  float* __restrict__ out,
                                                  int first, int last) {
    extern __shared__ uint4 xs4[];              // 32*97 uint4
    float* dtp = (float*)(xs4 + 32*97);         // 64 floats

    int p = blockIdx.x & 31, tile = blockIdx.x >> 5;
    int bk0 = 2*p, bk1 = bk0 + 1, b = p >> 2;
    int tid = threadIdx.x, w = tid >> 5, lane = tid & 31;

    // a-vectors in registers: a?v[2*kk+h] covers f = (kk*32+lane)*8 + 4h
    const float4* a0p = (const float4*)(g_aD + (size_t)bk0*DF);
    const float4* a1p = (const float4*)(g_aD + (size_t)bk1*DF);
    float4 a0v[6], a1v[6];
    #pragma unroll
    for (int kk = 0; kk < 3; kk++) {
        a0v[2*kk]   = a0p[(kk*32 + lane)*2];
        a0v[2*kk+1] = a0p[(kk*32 + lane)*2 + 1];
        a1v[2*kk]   = a1p[(kk*32 + lane)*2];
        a1v[2*kk+1] = a1p[(kk*32 + lane)*2 + 1];
    }
    float sA0 = g_sAD[bk0], sA1 = g_sAD[bk1];
    float be0 = g_beD[bk0], be1 = g_beD[bk1];
    float4 acc0 = {0,0,0,0}, acc1 = {0,0,0,0};
    float4 accT0 = {0,0,0,0}, accT1 = {0,0,0,0};
    float z0=0.f, z1=0.f, dd0=0.f, dd1=0.f, sm0=0.f, sm1=0.f;

    for (int cc = 0; cc < 4; cc++) {
        int j0 = tile*128 + cc*32;
        // Phase A: warp w stages tokens w*4..w*4+3 (fp16) AND computes delta-dots
        #pragma unroll
        for (int u = 0; u < 4; u++) {
            int t = w*4 + u;
            const uint4* gx = (const uint4*)(g_tok16 + (size_t)(b*N + j0 + t)*DF);
            float d0 = 0.f, d1 = 0.f;
            #pragma unroll
            for (int kk = 0; kk < 3; kk++) {
                uint4 xq = gx[kk*32 + lane];
                xs4[t*97 + kk*32 + lane] = xq;
                float2 x0 = h2f(xq.x), x1 = h2f(xq.y), x2 = h2f(xq.z), x3 = h2f(xq.w);
                float4 a0a = a0v[2*kk], a0b = a0v[2*kk+1];
                float4 a1a = a1v[2*kk], a1b = a1v[2*kk+1];
                d0 += a0a.x*x0.x + a0a.y*x0.y + a0a.z*x1.x + a0a.w*x1.y
                    + a0b.x*x2.x + a0b.y*x2.y + a0b.z*x3.x + a0b.w*x3.y;
                d1 += a1a.x*x0.x + a1a.y*x0.y + a1a.z*x1.x + a1a.w*x1.y
                    + a1b.x*x2.x + a1b.y*x2.y + a1b.z*x3.x + a1b.w*x3.y;
            }
            warp_reduce2(d0, d1, lane);
            if (lane == 0) { dtp[t] = d0; dtp[32 + t] = d1; }
        }
        __syncthreads();
        // Phase C: sigmoid weights (all warps redundantly; lane = token)
        int j = j0 + lane;
        float d0 = dtp[lane], d1 = dtp[32 + lane];
        float s0 = g_s[(size_t)bk0*N + j], s1 = g_s[(size_t)bk1*N + j];
        float m  = g_mean[b*N + j];
        float p0 = 1.f/(1.f + __expf(-(SCALE*(s0*(d0 - m*sA0) + be0))));
        float p1 = 1.f/(1.f + __expf(-(SCALE*(s1*(d1 - m*sA1) + be1))));
        float at0 = p0 + EPS_SA, at1 = p1 + EPS_SA;
        float c0 = at0*s0, c1 = at1*s1;
        if (w == 0) {
            z0 += at0; z1 += at1; dd0 += c0*m; dd1 += c1*m;
            if (first) { sm0 += s0*m; sm1 += s1*m; }
            if (last) {
                float mk0 = masks[(size_t)bk0*N + j];
                float mk1 = masks[(size_t)bk1*N + j];
                out[OBJ_SIZE + (size_t)(bk0*2)*N + j]   = at0*mk0;
                out[OBJ_SIZE + (size_t)(bk0*2+1)*N + j] = (1.f - p0 + EPS_SA)*mk0;
                out[OBJ_SIZE + (size_t)(bk1*2)*N + j]   = at1*mk1;
                out[OBJ_SIZE + (size_t)(bk1*2+1)*N + j] = (1.f - p1 + EPS_SA)*mk1;
            }
        }
        // Phase D: f-major accumulate; thread owns one uint2 column (4 halves)
        if (tid < 192) {
            const uint2* xs2 = (const uint2*)xs4;
            if (first) {
                #pragma unroll
                for (int t = 0; t < 32; t++) {
                    uint2 xq = xs2[t*194 + tid];
                    float2 xa = h2f(xq.x), xb = h2f(xq.y);
                    float c0t = __shfl_sync(0xffffffffu, c0, t);
                    float c1t = __shfl_sync(0xffffffffu, c1, t);
                    float s0t = __shfl_sync(0xffffffffu, s0, t);
                    float s1t = __shfl_sync(0xffffffffu, s1, t);
                    acc0.x += c0t*xa.x;  acc0.y += c0t*xa.y;  acc0.z += c0t*xb.x;  acc0.w += c0t*xb.y;
                    acc1.x += c1t*xa.x;  acc1.y += c1t*xa.y;  acc1.z += c1t*xb.x;  acc1.w += c1t*xb.y;
                    accT0.x += s0t*xa.x; accT0.y += s0t*xa.y; accT0.z += s0t*xb.x; accT0.w += s0t*xb.y;
                    accT1.x += s1t*xa.x; accT1.y += s1t*xa.y; accT1.z += s1t*xb.x; accT1.w += s1t*xb.y;
                }
            } else {
                #pragma unroll
                for (int t = 0; t < 32; t++) {
                    uint2 xq = xs2[t*194 + tid];
                    float2 xa = h2f(xq.x), xb = h2f(xq.y);
                    float c0t = __shfl_sync(0xffffffffu, c0, t);
                    float c1t = __shfl_sync(0xffffffffu, c1, t);
                    acc0.x += c0t*xa.x; acc0.y += c0t*xa.y; acc0.z += c0t*xb.x; acc0.w += c0t*xb.y;
                    acc1.x += c1t*xa.x; acc1.y += c1t*xa.y; acc1.z += c1t*xb.x; acc1.w += c1t*xb.y;
                }
            }
        }
        __syncthreads();
    }

    // epilogue: global accumulation
    if (tid < 192) {
        size_t f0 = (size_t)bk0*DF + tid*4;
        size_t f1 = (size_t)bk1*DF + tid*4;
        atomicAdd(&g_acc0[f0+0], acc0.x); atomicAdd(&g_acc0[f0+1], acc0.y);
        atomicAdd(&g_acc0[f0+2], acc0.z); atomicAdd(&g_acc0[f0+3], acc0.w);
        atomicAdd(&g_acc0[f1+0], acc1.x); atomicAdd(&g_acc0[f1+1], acc1.y);
        atomicAdd(&g_acc0[f1+2], acc1.z); atomicAdd(&g_acc0[f1+3], acc1.w);
        if (first) {
            atomicAdd(&g_T[f0+0], accT0.x); atomicAdd(&g_T[f0+1], accT0.y);
            atomicAdd(&g_T[f0+2], accT0.z); atomicAdd(&g_T[f0+3], accT0.w);
            atomicAdd(&g_T[f1+0], accT1.x); atomicAdd(&g_T[f1+1], accT1.y);
            atomicAdd(&g_T[f1+2], accT1.z); atomicAdd(&g_T[f1+3], accT1.w);
        }
    }
    if (w == 0) {
        warp_reduce2(z0, z1, lane);
        warp_reduce2(dd0, dd1, lane);
        if (first) warp_reduce2(sm0, sm1, lane);
        if (lane == 0) {
            atomicAdd(&g_z0[bk0], z0);  atomicAdd(&g_z0[bk1], z1);
            atomicAdd(&g_d0[bk0], dd0); atomicAdd(&g_d0[bk1], dd1);
            if (first) { atomicAdd(&g_sm[bk0], sm0); atomicAdd(&g_sm[bk1], sm1); }
        }
    }
}

// upd v3: 512 threads per slot row; 4-way f-splits.
__global__ void __launch_bounds__(512) upd_kernel(const float* __restrict__ ig,
                           const float* __restrict__ bih, const float* __restrict__ bhh,
                           const float* __restrict__ mg,  const float* __restrict__ mb,
                           const float* __restrict__ b1,  const float* __restrict__ b2,
                           float* __restrict__ out, int last) {
    __shared__ float gv[DF];
    __shared__ float su[DS], sh[DS], shh[DS], snews[DS];
    __shared__ float sy[4*DS];
    __shared__ float part[6][4][DS];
    __shared__ float red[DS];
    int r = blockIdx.x, tid = threadIdx.x;
    int col = tid & 127, q = tid >> 7;
    int bk = r >> 1, i = r & 1;
    const float ONE = 1.f + 2.f*EPS_SA;
    float Z0 = g_z0[bk], D0 = g_d0[bk];
    float Z = i ? (4096.f*ONE - Z0) : Z0;
    float D = i ? (g_sm[bk]*ONE - D0) : D0;
    for (int f = tid; f < DF; f += 512) {
        float A = g_acc0[(size_t)bk*DF + f];
        if (i) A = g_T[(size_t)bk*DF + f]*ONE - A;
        gv[f] = ig[f] * (A - D);
    }
    if (tid < DS) sh[tid] = g_slots[r*DS + tid];
    __syncthreads();
    {
        float a0=0.f,a1=0.f,a2=0.f,a3=0.f;
        int f0 = q*192;
        #pragma unroll 8
        for (int f = f0; f < f0+192; f += 4) {
            a0 += g_WvT[(f+0)*DS + col] * gv[f+0];
            a1 += g_WvT[(f+1)*DS + col] * gv[f+1];
            a2 += g_WvT[(f+2)*DS + col] * gv[f+2];
            a3 += g_WvT[(f+3)*DS + col] * gv[f+3];
        }
        part[0][q][col] = (a0+a1)+(a2+a3);
    }
    __syncthreads();
    if (tid < DS) su[tid] = ((part[0][0][tid] + part[0][1][tid]) +
                             (part[0][2][tid] + part[0][3][tid])) / Z + g_cv[tid];
    __syncthreads();
    {
        float gi0=0.f, gi1=0.f, gi2=0.f, gh0=0.f, gh1=0.f, gh2=0.f;
        int f0 = q*32;
        #pragma unroll 4
        for (int f = f0; f < f0+32; f++) {
            float uf = su[f], hf = sh[f];
            gi0 += g_WihT[f*(3*DS) + col]*uf;
            gi1 += g_WihT[f*(3*DS) + DS + col]*uf;
            gi2 += g_WihT[f*(3*DS) + 2*DS + col]*uf;
            gh0 += g_WhhT[f*(3*DS) + col]*hf;
            gh1 += g_WhhT[f*(3*DS) + DS + col]*hf;
            gh2 += g_WhhT[f*(3*DS) + 2*DS + col]*hf;
        }
        part[0][q][col] = gi0; part[1][q][col] = gi1; part[2][q][col] = gi2;
        part[3][q][col] = gh0; part[4][q][col] = gh1; part[5][q][col] = gh2;
    }
    __syncthreads();
    if (tid < DS) {
        int t = tid;
        float gi0 = bih[t]      + (part[0][0][t]+part[0][1][t])+(part[0][2][t]+part[0][3][t]);
        float gi1 = bih[DS+t]   + (part[1][0][t]+part[1][1][t])+(part[1][2][t]+part[1][3][t]);
        float gi2 = bih[2*DS+t] + (part[2][0][t]+part[2][1][t])+(part[2][2][t]+part[2][3][t]);
        float gh0 = bhh[t]      + (part[3][0][t]+part[3][1][t])+(part[3][2][t]+part[3][3][t]);
        float gh1 = bhh[DS+t]   + (part[4][0][t]+part[4][1][t])+(part[4][2][t]+part[4][3][t]);
        float gh2 = bhh[2*DS+t] + (part[5][0][t]+part[5][1][t])+(part[5][2][t]+part[5][3][t]);
        float rr = 1.f / (1.f + __expf(-(gi0 + gh0)));
        float zz = 1.f / (1.f + __expf(-(gi1 + gh1)));
        float nn = tanhf(gi2 + rr*gh2);
        snews[t] = (1.f - zz)*nn + zz*sh[t];
    }
    __syncthreads();
    if (tid < DS) red[tid] = snews[tid];
    __syncthreads();
    #pragma unroll
    for (int h2 = 64; h2; h2 >>= 1) { if (tid < h2) red[tid] += red[tid+h2]; __syncthreads(); }
    float m = red[0] * (1.f/DS);
    __syncthreads();
    if (tid < DS) { float dv = snews[tid] - m; red[tid] = dv*dv; }
    __syncthreads();
    #pragma unroll
    for (int h2 = 64; h2; h2 >>= 1) { if (tid < h2) red[tid] += red[tid+h2]; __syncthreads(); }
    float rstd = rsqrtf(red[0]*(1.f/DS) + 1e-5f);
    __syncthreads();
    if (tid < DS) shh[tid] = (snews[tid] - m)*rstd*mg[tid] + mb[tid];
    __syncthreads();
    {
        float aa = b1[tid];
        #pragma unroll 4
        for (int f = 0; f < DS; f++) aa += g_W1T[f*(4*DS) + tid] * shh[f];
        sy[tid] = 0.5f * aa * (1.f + erff(aa * 0.70710678118654752f));
    }
    __syncthreads();
    {
        float a0=0.f,a1=0.f,a2=0.f,a3=0.f;
        int o0 = q*128;
        #pragma unroll 8
        for (int o = o0; o < o0+128; o += 4) {
            a0 += g_W2T[(o+0)*DS + col]*sy[o+0];
            a1 += g_W2T[(o+1)*DS + col]*sy[o+1];
            a2 += g_W2T[(o+2)*DS + col]*sy[o+2];
            a3 += g_W2T[(o+3)*DS + col]*sy[o+3];
        }
        part[0][q][col] = (a0+a1)+(a2+a3);
    }
    __syncthreads();
    if (tid < DS) {
        float o2 = b2[tid] + (part[0][0][tid]+part[0][1][tid])
                           + (part[0][2][tid]+part[0][3][tid]);
        g_slots[r*DS + tid] = o2;
        if (last) out[r*DS + tid] = o2;
    }
}

// ------------------- launch -------------------
#define BIG_SMEM (32*97*16 + 256)   // 49920 bytes

extern "C" void kernel_launch(void* const* d_in, const int* in_sizes, int n_in,
                              void* d_out, int out_size) {
    const float* tokens = (const float*)d_in[0];
    const float* pslots = (const float*)d_in[1];
    const float* masks  = (const float*)d_in[2];
    const float* eps    = (const float*)d_in[3];
    const float* ig     = (const float*)d_in[4];
    const float* ib     = (const float*)d_in[5];
    const float* sg     = (const float*)d_in[6];
    const float* sb     = (const float*)d_in[7];
    const float* Wq     = (const float*)d_in[8];
    const float* Wk     = (const float*)d_in[9];
    const float* Wv     = (const float*)d_in[10];
    const float* Wih    = (const float*)d_in[11];
    const float* Whh    = (const float*)d_in[12];
    const float* bih    = (const float*)d_in[13];
    const float* bhh    = (const float*)d_in[14];
    const float* mg     = (const float*)d_in[15];
    const float* mb     = (const float*)d_in[16];
    const float* W1     = (const float*)d_in[17];
    const float* b1     = (const float*)d_in[18];
    const float* W2     = (const float*)d_in[19];
    const float* b2     = (const float*)d_in[20];
    float* out = (float*)d_out;

    cudaFuncSetAttribute(big_kernel, cudaFuncAttributeMaxDynamicSharedMemorySize, BIG_SMEM);

    stats_kernel<<<B*N/8, 256>>>(tokens);                               // 0
    dss_kernel<<<BK, 256>>>(masks, Wk, ig, ib);                         // 1
    qa_kernel<<<BK*3, 256>>>(pslots, eps, Wq, Wk, sg, sb, ig, ib, 1);   // 2
    big_kernel<<<32*32, 256, BIG_SMEM>>>(masks, out, 1, 0);             // 3 (profiled)
    tr_kernel<<<(DF*DS + 2*DS*3*DS + 2*DS*4*DS + 255)/256, 256>>>(Wv, Wih, Whh, W1, W2); // 4
    cv_kernel<<<16, 256>>>(Wv, ib);                                     // 5
    upd_kernel<<<NS, 512>>>(ig, bih, bhh, mg, mb, b1, b2, out, 0);      // 6

    // iteration 1
    qa_kernel<<<BK*3, 256>>>(pslots, eps, Wq, Wk, sg, sb, ig, ib, 0);
    big_kernel<<<32*32, 256, BIG_SMEM>>>(masks, out, 0, 0);
    upd_kernel<<<NS, 512>>>(ig, bih, bhh, mg, mb, b1, b2, out, 0);
    // iteration 2 (last)
    qa_kernel<<<BK*3, 256>>>(pslots, eps, Wq, Wk, sg, sb, ig, ib, 0);
    big_kernel<<<32*32, 256, BIG_SMEM>>>(masks, out, 0, 1);
    upd_kernel<<<NS, 512>>>(ig, bih, bhh, mg, mb, b1, b2, out, 1);
}

// round 15
// speedup vs baseline: 1.5407x; 1.0133x over previous
#include <cuda_runtime.h>
#include <cuda_fp16.h>
#include <math.h>

#define B 8
#define N 4096
#define DF 768
#define K1 8
#define K2 2
#define DS 128
#define BK (B*K1)        // 64
#define NS (BK*K2)       // 128 slot rows
#define SCALE 0.088388347648318447f
#define EPS_SA 1e-8f
#define OBJ_SIZE (NS*DS)

// ------------------- scratch (device globals) -------------------
__device__ float g_mean[B*N];
__device__ float g_var[B*N];
__device__ float g_s[BK*N];
__device__ float g_sm[BK];
__device__ __align__(16) float g_T[BK*DF];
__device__ float g_slots[NS*DS];
__device__ __align__(16) float g_aD[BK*DF];
__device__ float g_sAD[BK];
__device__ float g_beD[BK];
__device__ __align__(16) float g_acc0[BK*DF];
__device__ float g_z0[BK];
__device__ float g_d0[BK];
__device__ float g_cv[DS];
__device__ float g_kg[BK < DS ? DS : DS];
__device__ float g_kb[DS];
__device__ __align__(16) __half g_tok16[(size_t)B*N*DF];   // fp16 tokens (50MB)
// transposed weights
__device__ float g_WvT[DF*DS];
__device__ float g_WihT[DS*3*DS];
__device__ float g_WhhT[DS*3*DS];
__device__ float g_W1T[DS*4*DS];
__device__ float g_W2T[4*DS*DS];

__device__ __forceinline__ void warp_reduce2(float& x, float& y, int lane) {
    float xo = __shfl_xor_sync(0xffffffffu, x, 16);
    float yo = __shfl_xor_sync(0xffffffffu, y, 16);
    float v  = (lane < 16) ? (x + xo) : (y + yo);
    #pragma unroll
    for (int off = 8; off; off >>= 1) v += __shfl_xor_sync(0xffffffffu, v, off);
    x = __shfl_sync(0xffffffffu, v, 0);
    y = __shfl_sync(0xffffffffu, v, 16);
}

__device__ __forceinline__ float block_reduce_256(float v, float* red, int tid) {
    red[tid] = v; __syncthreads();
    #pragma unroll
    for (int h = 128; h > 0; h >>= 1) {
        if (tid < h) red[tid] += red[tid + h];
        __syncthreads();
    }
    float r = red[0];
    __syncthreads();
    return r;
}

__device__ __forceinline__ float2 h2f(unsigned u) {
    __half2 h; *(unsigned*)&h = u;
    return __half22float2(h);
}

// packed dual-FMA: d += a*b elementwise on float2, via Blackwell fma.rn.f32x2.
__device__ __forceinline__ void fma2(float2& d, float2 a, float2 b) {
    asm("{\n\t"
        ".reg .b64 ra, rb, rd;\n\t"
        "mov.b64 ra, {%2, %3};\n\t"
        "mov.b64 rb, {%4, %5};\n\t"
        "mov.b64 rd, {%0, %1};\n\t"
        "fma.rn.f32x2 rd, ra, rb, rd;\n\t"
        "mov.b64 {%0, %1}, rd;\n\t"
        "}"
        : "+f"(d.x), "+f"(d.y)
        : "f"(a.x), "f"(a.y), "f"(b.x), "f"(b.y));
}

// ------------------- one-time kernels -------------------
// per-token mean/var over DF + fp16 conversion.  grid B*N/8 blocks of 256 (warp/row)
__global__ void stats_kernel(const float* __restrict__ tokens) {
    int row  = blockIdx.x * 8 + (threadIdx.x >> 5);
    int lane = threadIdx.x & 31;
    const float4* xp = (const float4*)(tokens + (size_t)row * DF);
    uint2* hp = (uint2*)(g_tok16 + (size_t)row * DF);
    float s = 0.f, s2 = 0.f;
    #pragma unroll
    for (int k = 0; k < 6; k++) {
        float4 v = xp[k*32 + lane];
        s  += v.x + v.y + v.z + v.w;
        s2 += v.x*v.x + v.y*v.y + v.z*v.z + v.w*v.w;
        __half2 h0 = __floats2half2_rn(v.x, v.y);
        __half2 h1 = __floats2half2_rn(v.z, v.w);
        uint2 u; u.x = *(unsigned*)&h0; u.y = *(unsigned*)&h1;
        hp[k*32 + lane] = u;
    }
    #pragma unroll
    for (int off = 16; off; off >>= 1) {
        s  += __shfl_xor_sync(0xffffffffu, s,  off);
        s2 += __shfl_xor_sync(0xffffffffu, s2, off);
    }
    if (lane == 0) {
        float m = s * (1.f/DF);
        g_mean[row] = m;
        g_var[row]  = s2 * (1.f/DF) - m*m;
    }
}

// fused denom + s; blocks 0-31 additionally compute kg/kb.  grid BK blocks of 256
__global__ void dss_kernel(const float* __restrict__ masks, const float* __restrict__ Wk,
                           const float* __restrict__ ig, const float* __restrict__ ib) {
    __shared__ float red[256];
    int bk = blockIdx.x, b = bk >> 3, tid = threadIdx.x;
    float s = 0.f;
    for (int j = tid; j < N; j += 256) s += masks[(size_t)bk*N + j];
    float denom = block_reduce_256(s, red, tid) * (1.f/N);
    int good = denom > 1e-6f;
    float inv = 1.f / (denom + 1e-6f);
    for (int j = tid; j < N; j += 256) {
        float w = good ? masks[(size_t)bk*N + j] * inv : 1.0f;
        float v = g_var[b*N + j];
        g_s[(size_t)bk*N + j] = w * rsqrtf(w*w*v + 1e-5f);
    }
    if (bk < 32) {
        int w = tid >> 5, lane = tid & 31;
        int c = (bk & 15)*8 + w;
        const float* vv = (bk < 16) ? ig : ib;
        float acc = 0.f;
        #pragma unroll
        for (int k = 0; k < 24; k++) {
            int f = k*32 + lane;
            acc += Wk[(size_t)c*DF + f] * vv[f];
        }
        #pragma unroll
        for (int off = 16; off; off >>= 1) acc += __shfl_xor_sync(0xffffffffu, acc, off);
        if (lane == 0) { if (bk < 16) g_kg[c] = acc; else g_kb[c] = acc; }
    }
}

// transpose weight matrices (Wv, Wih, Whh, W1, W2)
__global__ void tr_kernel(const float* __restrict__ Wv,
                          const float* __restrict__ Wih, const float* __restrict__ Whh,
                          const float* __restrict__ W1, const float* __restrict__ W2) {
    int i = blockIdx.x*256 + threadIdx.x;
    if (i < DF*DS) { int f = i/DS, o = i%DS; g_WvT[i] = Wv[o*DF + f]; return; }
    i -= DF*DS;
    if (i < DS*3*DS) { int f = i/(3*DS), o = i%(3*DS); g_WihT[i] = Wih[o*DS + f]; return; }
    i -= DS*3*DS;
    if (i < DS*3*DS) { int f = i/(3*DS), o = i%(3*DS); g_WhhT[i] = Whh[o*DS + f]; return; }
    i -= DS*3*DS;
    if (i < DS*4*DS) { int f = i/(4*DS), o = i%(4*DS); g_W1T[i] = W1[o*DS + f]; return; }
    i -= DS*4*DS;
    if (i < 4*DS*DS) { int o = i/DS, t = i%DS; g_W2T[i] = W2[t*4*DS + o]; return; }
}

// cv = Wv @ ln_in_b.  grid 16 blocks x 256 (warp per output col)
__global__ void cv_kernel(const float* __restrict__ Wv, const float* __restrict__ lnb) {
    int col  = blockIdx.x*8 + (threadIdx.x >> 5);
    int lane = threadIdx.x & 31;
    float a = 0.f;
    #pragma unroll
    for (int k = 0; k < 24; k++) {
        int f = k*32 + lane;
        a += Wv[(size_t)col*DF + f] * lnb[f];
    }
    #pragma unroll
    for (int off = 16; off; off >>= 1) a += __shfl_xor_sync(0xffffffffu, a, off);
    if (lane == 0) g_cv[col] = a;
}

// ------------------- per-iteration kernels -------------------
// grid = BK*3 blocks: (bk, ff-slice).
__global__ void qa_kernel(const float* __restrict__ ps, const float* __restrict__ eps,
                          const float* __restrict__ Wq, const float* __restrict__ Wk,
                          const float* __restrict__ sg, const float* __restrict__ sb,
                          const float* __restrict__ ig, const float* __restrict__ ib,
                          int first) {
    __shared__ float sn[2][DS], qsh[2][DS], qD[DS], red[256];
    int bk = blockIdx.x / 3, ff = blockIdx.x % 3;
    int tid = threadIdx.x;
    int half = tid >> 7, t = tid & 127;
    int r = bk*2 + half;
    float val;
    if (first) {
        val = ps[bk*DS + t] + 0.01f * eps[r*DS + t];
        if (ff == 0) g_slots[r*DS + t] = val;
    } else {
        val = g_slots[r*DS + t];
    }
    red[tid] = val; __syncthreads();
    #pragma unroll
    for (int h = 64; h; h >>= 1) { if (t < h) red[tid] += red[tid + h]; __syncthreads(); }
    float m = red[half*128] * (1.f/DS);
    __syncthreads();
    float dv = val - m;
    red[tid] = dv*dv; __syncthreads();
    #pragma unroll
    for (int h = 64; h; h >>= 1) { if (t < h) red[tid] += red[tid + h]; __syncthreads(); }
    float rstd = rsqrtf(red[half*128] * (1.f/DS) + 1e-5f);
    __syncthreads();
    sn[half][t] = dv * rstd * sg[t] + sb[t];
    __syncthreads();
    {
        float q0 = 0.f, q1 = 0.f;
        #pragma unroll 4
        for (int f = 0; f < DS; f += 2) {
            q0 += Wq[t*DS + f]   * sn[half][f];
            q1 += Wq[t*DS + f+1] * sn[half][f+1];
        }
        qsh[half][t] = q0 + q1;
    }
    __syncthreads();
    if (tid < DS) qD[tid] = qsh[0][tid] - qsh[1][tid];
    __syncthreads();
    {
        int f = ff*256 + tid;
        float r0=0.f, r1=0.f, r2=0.f, r3=0.f;
        #pragma unroll 4
        for (int c = 0; c < DS; c += 4) {
            r0 += Wk[c*DF + f]     * qD[c];
            r1 += Wk[(c+1)*DF + f] * qD[c+1];
            r2 += Wk[(c+2)*DF + f] * qD[c+2];
            r3 += Wk[(c+3)*DF + f] * qD[c+3];
        }
        float raw = (r0+r1)+(r2+r3);
        g_aD[(size_t)bk*DF + f]   = raw * ig[f];
        g_acc0[(size_t)bk*DF + f] = 0.f;
        if (first) g_T[(size_t)bk*DF + f] = 0.f;
    }
    if (ff == 0) {
        float psm = (tid < DS) ? qD[tid]*g_kg[tid] : 0.f;
        float pbe = (tid < DS) ? qD[tid]*g_kb[tid] : 0.f;
        float ts = block_reduce_256(psm, red, tid);
        float tb = block_reduce_256(pbe, red, tid);
        if (tid == 0) {
            g_sAD[bk] = ts; g_beD[bk] = tb;
            g_z0[bk] = 0.f; g_d0[bk] = 0.f;
            if (first) g_sm[bk] = 0.f;
        }
    }
}

// Phased big kernel, fp16 tokens, double-buffered smem, packed f32x2 FMA.
// block = 256, pair of bks, 4 chunks of 32 tokens; one barrier per chunk.
__global__ void __launch_bounds__(256, 2) big_kernel(const float* __restrict__ masks,
                                                     float* __restrict__ out,
                                                     int first, int last) {
    extern __shared__ uint4 xs4[];               // 2 buffers of 32*97 uint4
    float* dtp = (float*)(xs4 + 2*32*97);        // 2 buffers of 64 floats

    int p = blockIdx.x & 31, tile = blockIdx.x >> 5;
    int bk0 = 2*p, bk1 = bk0 + 1, b = p >> 2;
    int tid = threadIdx.x, w = tid >> 5, lane = tid & 31;

    // a-vectors as float2 pairs: a?v[kk*4+h] covers f = (kk*32+lane)*8 + 2h
    const float2* a0p = (const float2*)(g_aD + (size_t)bk0*DF);
    const float2* a1p = (const float2*)(g_aD + (size_t)bk1*DF);
    float2 a0v[12], a1v[12];
    #pragma unroll
    for (int kk = 0; kk < 3; kk++) {
        #pragma unroll
        for (int h = 0; h < 4; h++) {
            a0v[kk*4+h] = a0p[(kk*32 + lane)*4 + h];
            a1v[kk*4+h] = a1p[(kk*32 + lane)*4 + h];
        }
    }
    float sA0 = g_sAD[bk0], sA1 = g_sAD[bk1];
    float be0 = g_beD[bk0], be1 = g_beD[bk1];
    float2 acc0a = {0,0}, acc0b = {0,0}, acc1a = {0,0}, acc1b = {0,0};
    float2 accT0a = {0,0}, accT0b = {0,0}, accT1a = {0,0}, accT1b = {0,0};
    float z0=0.f, z1=0.f, dd0=0.f, dd1=0.f, sm0=0.f, sm1=0.f;

    // stage chunk cc into buffer cc&1 and compute its delta-dots
    auto stageA = [&](int cc) {
        int j0 = tile*128 + cc*32;
        uint4* xb = xs4 + (cc & 1)*(32*97);
        float* dt = dtp + (cc & 1)*64;
        #pragma unroll
        for (int u = 0; u < 4; u++) {
            int t = w*4 + u;
            const uint4* gx = (const uint4*)(g_tok16 + (size_t)(b*N + j0 + t)*DF);
            float2 d0p = {0,0}, d1p = {0,0};
            #pragma unroll
            for (int kk = 0; kk < 3; kk++) {
                uint4 xq = gx[kk*32 + lane];
                xb[t*97 + kk*32 + lane] = xq;
                float2 x0 = h2f(xq.x), x1 = h2f(xq.y), x2 = h2f(xq.z), x3 = h2f(xq.w);
                fma2(d0p, a0v[kk*4+0], x0); fma2(d0p, a0v[kk*4+1], x1);
                fma2(d0p, a0v[kk*4+2], x2); fma2(d0p, a0v[kk*4+3], x3);
                fma2(d1p, a1v[kk*4+0], x0); fma2(d1p, a1v[kk*4+1], x1);
                fma2(d1p, a1v[kk*4+2], x2); fma2(d1p, a1v[kk*4+3], x3);
            }
            float d0 = d0p.x + d0p.y, d1 = d1p.x + d1p.y;
            warp_reduce2(d0, d1, lane);
            if (lane == 0) { dt[t] = d0; dt[32 + t] = d1; }
        }
    };

    stageA(0);
    __syncthreads();

    for (int cc = 0; cc < 4; cc++) {
        int j0 = tile*128 + cc*32;
        float* dt = dtp + (cc & 1)*64;
        // Phase C: sigmoid weights (all warps redundantly; lane = token)
        int j = j0 + lane;
        float d0 = dt[lane], d1 = dt[32 + lane];
        float s0 = g_s[(size_t)bk0*N + j], s1 = g_s[(size_t)bk1*N + j];
        float m  = g_mean[b*N + j];
        float p0 = 1.f/(1.f + __expf(-(SCALE*(s0*(d0 - m*sA0) + be0))));
        float p1 = 1.f/(1.f + __expf(-(SCALE*(s1*(d1 - m*sA1) + be1))));
        float at0 = p0 + EPS_SA, at1 = p1 + EPS_SA;
        float c0 = at0*s0, c1 = at1*s1;
        if (w == 0) {
            z0 += at0; z1 += at1; dd0 += c0*m; dd1 += c1*m;
            if (first) { sm0 += s0*m; sm1 += s1*m; }
            if (last) {
                float mk0 = masks[(size_t)bk0*N + j];
                float mk1 = masks[(size_t)bk1*N + j];
                out[OBJ_SIZE + (size_t)(bk0*2)*N + j]   = at0*mk0;
                out[OBJ_SIZE + (size_t)(bk0*2+1)*N + j] = (1.f - p0 + EPS_SA)*mk0;
                out[OBJ_SIZE + (size_t)(bk1*2)*N + j]   = at1*mk1;
                out[OBJ_SIZE + (size_t)(bk1*2+1)*N + j] = (1.f - p1 + EPS_SA)*mk1;
            }
        }
        // Phase D: f-major accumulate; thread owns one uint2 column (4 halves)
        if (tid < 192) {
            const uint2* xs2 = (const uint2*)(xs4 + (cc & 1)*(32*97));
            if (first) {
                #pragma unroll
                for (int t = 0; t < 32; t++) {
                    uint2 xq = xs2[t*194 + tid];
                    float2 xa = h2f(xq.x), xb2 = h2f(xq.y);
                    float c0t = __shfl_sync(0xffffffffu, c0, t);
                    float c1t = __shfl_sync(0xffffffffu, c1, t);
                    float s0t = __shfl_sync(0xffffffffu, s0, t);
                    float s1t = __shfl_sync(0xffffffffu, s1, t);
                    float2 pc0 = {c0t, c0t}, pc1 = {c1t, c1t};
                    float2 ps0 = {s0t, s0t}, ps1 = {s1t, s1t};
                    fma2(acc0a, pc0, xa); fma2(acc0b, pc0, xb2);
                    fma2(acc1a, pc1, xa); fma2(acc1b, pc1, xb2);
                    fma2(accT0a, ps0, xa); fma2(accT0b, ps0, xb2);
                    fma2(accT1a, ps1, xa); fma2(accT1b, ps1, xb2);
                }
            } else {
                #pragma unroll
                for (int t = 0; t < 32; t++) {
                    uint2 xq = xs2[t*194 + tid];
                    float2 xa = h2f(xq.x), xb2 = h2f(xq.y);
                    float c0t = __shfl_sync(0xffffffffu, c0, t);
                    float c1t = __shfl_sync(0xffffffffu, c1, t);
                    float2 pc0 = {c0t, c0t}, pc1 = {c1t, c1t};
                    fma2(acc0a, pc0, xa); fma2(acc0b, pc0, xb2);
                    fma2(acc1a, pc1, xa); fma2(acc1b, pc1, xb2);
                }
            }
        }
        if (cc < 3) stageA(cc + 1);   // fill other buffer; no barrier needed before
        __syncthreads();
    }

    // epilogue: global accumulation
    if (tid < 192) {
        size_t f0 = (size_t)bk0*DF + tid*4;
        size_t f1 = (size_t)bk1*DF + tid*4;
        atomicAdd(&g_acc0[f0+0], acc0a.x); atomicAdd(&g_acc0[f0+1], acc0a.y);
        atomicAdd(&g_acc0[f0+2], acc0b.x); atomicAdd(&g_acc0[f0+3], acc0b.y);
        atomicAdd(&g_acc0[f1+0], acc1a.x); atomicAdd(&g_acc0[f1+1], acc1a.y);
        atomicAdd(&g_acc0[f1+2], acc1b.x); atomicAdd(&g_acc0[f1+3], acc1b.y);
        if (first) {
            atomicAdd(&g_T[f0+0], accT0a.x); atomicAdd(&g_T[f0+1], accT0a.y);
            atomicAdd(&g_T[f0+2], accT0b.x); atomicAdd(&g_T[f0+3], accT0b.y);
            atomicAdd(&g_T[f1+0], accT1a.x); atomicAdd(&g_T[f1+1], accT1a.y);
            atomicAdd(&g_T[f1+2], accT1b.x); atomicAdd(&g_T[f1+3], accT1b.y);
        }
    }
    if (w == 0) {
        warp_reduce2(z0, z1, lane);
        warp_reduce2(dd0, dd1, lane);
        if (first) warp_reduce2(sm0, sm1, lane);
        if (lane == 0) {
            atomicAdd(&g_z0[bk0], z0);  atomicAdd(&g_z0[bk1], z1);
            atomicAdd(&g_d0[bk0], dd0); atomicAdd(&g_d0[bk1], dd1);
            if (first) { atomicAdd(&g_sm[bk0], sm0); atomicAdd(&g_sm[bk1], sm1); }
        }
    }
}

// upd v3: 512 threads per slot row; 4-way f-splits.
__global__ void __launch_bounds__(512) upd_kernel(const float* __restrict__ ig,
                           const float* __restrict__ bih, const float* __restrict__ bhh,
                           const float* __restrict__ mg,  const float* __restrict__ mb,
                           const float* __restrict__ b1,  const float* __restrict__ b2,
                           float* __restrict__ out, int last) {
    __shared__ float gv[DF];
    __shared__ float su[DS], sh[DS], shh[DS], snews[DS];
    __shared__ float sy[4*DS];
    __shared__ float part[6][4][DS];
    __shared__ float red[DS];
    int r = blockIdx.x, tid = threadIdx.x;
    int col = tid & 127, q = tid >> 7;
    int bk = r >> 1, i = r & 1;
    const float ONE = 1.f + 2.f*EPS_SA;
    float Z0 = g_z0[bk], D0 = g_d0[bk];
    float Z = i ? (4096.f*ONE - Z0) : Z0;
    float D = i ? (g_sm[bk]*ONE - D0) : D0;
    for (int f = tid; f < DF; f += 512) {
        float A = g_acc0[(size_t)bk*DF + f];
        if (i) A = g_T[(size_t)bk*DF + f]*ONE - A;
        gv[f] = ig[f] * (A - D);
    }
    if (tid < DS) sh[tid] = g_slots[r*DS + tid];
    __syncthreads();
    {
        float a0=0.f,a1=0.f,a2=0.f,a3=0.f;
        int f0 = q*192;
        #pragma unroll 8
        for (int f = f0; f < f0+192; f += 4) {
            a0 += g_WvT[(f+0)*DS + col] * gv[f+0];
            a1 += g_WvT[(f+1)*DS + col] * gv[f+1];
            a2 += g_WvT[(f+2)*DS + col] * gv[f+2];
            a3 += g_WvT[(f+3)*DS + col] * gv[f+3];
        }
        part[0][q][col] = (a0+a1)+(a2+a3);
    }
    __syncthreads();
    if (tid < DS) su[tid] = ((part[0][0][tid] + part[0][1][tid]) +
                             (part[0][2][tid] + part[0][3][tid])) / Z + g_cv[tid];
    __syncthreads();
    {
        float gi0=0.f, gi1=0.f, gi2=0.f, gh0=0.f, gh1=0.f, gh2=0.f;
        int f0 = q*32;
        #pragma unroll 4
        for (int f = f0; f < f0+32; f++) {
            float uf = su[f], hf = sh[f];
            gi0 += g_WihT[f*(3*DS) + col]*uf;
            gi1 += g_WihT[f*(3*DS) + DS + col]*uf;
            gi2 += g_WihT[f*(3*DS) + 2*DS + col]*uf;
            gh0 += g_WhhT[f*(3*DS) + col]*hf;
            gh1 += g_WhhT[f*(3*DS) + DS + col]*hf;
            gh2 += g_WhhT[f*(3*DS) + 2*DS + col]*hf;
        }
        part[0][q][col] = gi0; part[1][q][col] = gi1; part[2][q][col] = gi2;
        part[3][q][col] = gh0; part[4][q][col] = gh1; part[5][q][col] = gh2;
    }
    __syncthreads();
    if (tid < DS) {
        int t = tid;
        float gi0 = bih[t]      + (part[0][0][t]+part[0][1][t])+(part[0][2][t]+part[0][3][t]);
        float gi1 = bih[DS+t]   + (part[1][0][t]+part[1][1][t])+(part[1][2][t]+part[1][3][t]);
        float gi2 = bih[2*DS+t] + (part[2][0][t]+part[2][1][t])+(part[2][2][t]+part[2][3][t]);
        float gh0 = bhh[t]      + (part[3][0][t]+part[3][1][t])+(part[3][2][t]+part[3][3][t]);
        float gh1 = bhh[DS+t]   + (part[4][0][t]+part[4][1][t])+(part[4][2][t]+part[4][3][t]);
        float gh2 = bhh[2*DS+t] + (part[5][0][t]+part[5][1][t])+(part[5][2][t]+part[5][3][t]);
        float rr = 1.f / (1.f + __expf(-(gi0 + gh0)));
        float zz = 1.f / (1.f + __expf(-(gi1 + gh1)));
        float nn = tanhf(gi2 + rr*gh2);
        snews[t] = (1.f - zz)*nn + zz*sh[t];
    }
    __syncthreads();
    if (tid < DS) red[tid] = snews[tid];
    __syncthreads();
    #pragma unroll
    for (int h2 = 64; h2; h2 >>= 1) { if (tid < h2) red[tid] += red[tid+h2]; __syncthreads(); }
    float m = red[0] * (1.f/DS);
    __syncthreads();
    if (tid < DS) { float dv = snews[tid] - m; red[tid] = dv*dv; }
    __syncthreads();
    #pragma unroll
    for (int h2 = 64; h2; h2 >>= 1) { if (tid < h2) red[tid] += red[tid+h2]; __syncthreads(); }
    float rstd = rsqrtf(red[0]*(1.f/DS) + 1e-5f);
    __syncthreads();
    if (tid < DS) shh[tid] = (snews[tid] - m)*rstd*mg[tid] + mb[tid];
    __syncthreads();
    {
        float aa = b1[tid];
        #pragma unroll 4
        for (int f = 0; f < DS; f++) aa += g_W1T[f*(4*DS) + tid] * shh[f];
        sy[tid] = 0.5f * aa * (1.f + erff(aa * 0.70710678118654752f));
    }
    __syncthreads();
    {
        float a0=0.f,a1=0.f,a2=0.f,a3=0.f;
        int o0 = q*128;
        #pragma unroll 8
        for (int o = o0; o < o0+128; o += 4) {
            a0 += g_W2T[(o+0)*DS + col]*sy[o+0];
            a1 += g_W2T[(o+1)*DS + col]*sy[o+1];
            a2 += g_W2T[(o+2)*DS + col]*sy[o+2];
            a3 += g_W2T[(o+3)*DS + col]*sy[o+3];
        }
        part[0][q][col] = (a0+a1)+(a2+a3);
    }
    __syncthreads();
    if (tid < DS) {
        float o2 = b2[tid] + (part[0][0][tid]+part[0][1][tid])
                           + (part[0][2][tid]+part[0][3][tid]);
        g_slots[r*DS + tid] = o2;
        if (last) out[r*DS + tid] = o2;
    }
}

// ------------------- launch -------------------
#define BIG_SMEM (2*32*97*16 + 2*64*4)   // 99840 bytes

extern "C" void kernel_launch(void* const* d_in, const int* in_sizes, int n_in,
                              void* d_out, int out_size) {
    const float* tokens = (const float*)d_in[0];
    const float* pslots = (const float*)d_in[1];
    const float* masks  = (const float*)d_in[2];
    const float* eps    = (const float*)d_in[3];
    const float* ig     = (const float*)d_in[4];
    const float* ib     = (const float*)d_in[5];
    const float* sg     = (const float*)d_in[6];
    const float* sb     = (const float*)d_in[7];
    const float* Wq     = (const float*)d_in[8];
    const float* Wk     = (const float*)d_in[9];
    const float* Wv     = (const float*)d_in[10];
    const float* Wih    = (const float*)d_in[11];
    const float* Whh    = (const float*)d_in[12];
    const float* bih    = (const float*)d_in[13];
    const float* bhh    = (const float*)d_in[14];
    const float* mg     = (const float*)d_in[15];
    const float* mb     = (const float*)d_in[16];
    const float* W1     = (const float*)d_in[17];
    const float* b1     = (const float*)d_in[18];
    const float* W2     = (const float*)d_in[19];
    const float* b2     = (const float*)d_in[20];
    float* out = (float*)d_out;

    cudaFuncSetAttribute(big_kernel, cudaFuncAttributeMaxDynamicSharedMemorySize, BIG_SMEM);

    stats_kernel<<<B*N/8, 256>>>(tokens);                               // 0
    dss_kernel<<<BK, 256>>>(masks, Wk, ig, ib);                         // 1
    qa_kernel<<<BK*3, 256>>>(pslots, eps, Wq, Wk, sg, sb, ig, ib, 1);   // 2
    big_kernel<<<32*32, 256, BIG_SMEM>>>(masks, out, 1, 0);             // 3 (profiled)
    tr_kernel<<<(DF*DS + 2*DS*3*DS + 2*DS*4*DS + 255)/256, 256>>>(Wv, Wih, Whh, W1, W2); // 4
    cv_kernel<<<16, 256>>>(Wv, ib);                                     // 5
    upd_kernel<<<NS, 512>>>(ig, bih, bhh, mg, mb, b1, b2, out, 0);      // 6

    // iteration 1
    qa_kernel<<<BK*3, 256>>>(pslots, eps, Wq, Wk, sg, sb, ig, ib, 0);
    big_kernel<<<32*32, 256, BIG_SMEM>>>(masks, out, 0, 0);
    upd_kernel<<<NS, 512>>>(ig, bih, bhh, mg, mb, b1, b2, out, 0);
    // iteration 2 (last)
    qa_kernel<<<BK*3, 256>>>(pslots, eps, Wq, Wk, sg, sb, ig, ib, 0);
    big_kernel<<<32*32, 256, BIG_SMEM>>>(masks, out, 0, 1);
    upd_kernel<<<NS, 512>>>(ig, bih, bhh, mg, mb, b1, b2, out, 1);
}